// round 9
// baseline (speedup 1.0000x reference)
#include <cuda_runtime.h>
#include <math.h>

#define N_ITER 10
#define UPD_CHUNK 24

static __device__ float d_p[5];                     // separable 1D psf
static __device__ float d_E[96 * 192 * 192];        // generic path only
static __device__ float d_A[192 * 192 * 192];       // ping
static __device__ float d_B[192 * 192 * 192];       // generic path pong

// ---------------------------------------------------------------------------
// packed f32x2 helpers (Blackwell)
// ---------------------------------------------------------------------------
__device__ __forceinline__ unsigned long long pk2(float lo, float hi) {
    unsigned long long r;
    asm("mov.b64 %0, {%1, %2};" : "=l"(r) : "f"(lo), "f"(hi));
    return r;
}
__device__ __forceinline__ void upk2(unsigned long long v, float& lo, float& hi) {
    asm("mov.b64 {%0, %1}, %2;" : "=f"(lo), "=f"(hi) : "l"(v));
}
__device__ __forceinline__ unsigned long long fma2_(unsigned long long a,
                                                    unsigned long long b,
                                                    unsigned long long c) {
    unsigned long long d;
    asm("fma.rn.f32x2 %0, %1, %2, %3;" : "=l"(d) : "l"(a), "l"(b), "l"(c));
    return d;
}
__device__ __forceinline__ unsigned long long mul2_(unsigned long long a,
                                                    unsigned long long b) {
    unsigned long long d;
    asm("mul.rn.f32x2 %0, %1, %2;" : "=l"(d) : "l"(a), "l"(b));
    return d;
}

// ---------------------------------------------------------------------------
__global__ void init_p_kernel(const float* __restrict__ psf) {
    int i = threadIdx.x;
    if (i < 5) {
        float s = 0.f;
        for (int j = 0; j < 25; ++j) s += psf[i * 25 + j];
        d_p[i] = s;
    }
}

// ===========================================================================
// MEGA kernel (spec: D=H=W=192, NS=96, stride==2).
// One block: 32x32 xy output tile, ZC z-planes. Per z-pair:
//   - load 2 new x-planes (40x40 halo) into an 8-slot smem ring
//   - compute E(h+1) = conv_xy(conv_xy(conv_z(x)[2h+2]) - slice[h+1]) into
//     a 3-slot smem E ring (5 separable stages)
//   - update voxels (z, z+1): data term from E ring + 26-neighbor
//     regularizer from the x ring (packed f32x2 pair math)
// ===========================================================================
template <int D, int H, int W, int NS, int ZC>
__global__ __launch_bounds__(256, 2) void mega_t(
    const float* __restrict__ xin, const float* __restrict__ slices,
    float* __restrict__ xout, const int* __restrict__ stridep, int do_relu) {
    constexpr int HW = H * W;
    constexpr int XPL = 40 * 42;     // x-ring plane floats (40 rows x 42 pitch)
    constexpr int EPL = 32 * 33;     // E-ring plane floats
    extern __shared__ float smdyn[];
    float* xr = smdyn;               // [8][XPL]
    float* Er = smdyn + 8 * XPL;     // [3][EPL]
    float* sZ = Er + 3 * EPL;        // [40][42] temp (stage 1 out)
    float* sA = sZ + XPL;            // [40][36] temp (stage 2 out)
    float* sF = sZ;                  // [36][37] overlay on sZ (stage 3 out)
    float* sB = sA;                  // [36][33] overlay on sA (stage 4 out)

    if (*stridep != 2) return;       // spec path only (uniform, pre-barrier)

    const int x0 = blockIdx.x * 32, y0 = blockIdx.y * 32;
    const int zb = blockIdx.z * ZC;  // multiple of ZC (even)
    const int tx = threadIdx.x, ty = threadIdx.y;

    const float p0 = d_p[0], p1 = d_p[1], p2 = d_p[2], p3 = d_p[3], p4 = d_p[4];
    const float w1 = (float)(1.0 / (1.0 * 0.1 * 0.1));
    const float w2 = (float)(1.0 / (2.0 * 0.1 * 0.1));
    const float w3 = (float)(1.0 / (3.0 * 0.1 * 0.1));

    const bool intXY = (x0 >= 4) && (x0 + 36 <= W) && (y0 >= 4) && (y0 + 36 <= H);

    // ---- load one x-plane (40x40 halo, zero outside volume) into ring ----
    auto loadPlane = [&](int z) {
        float* pl = xr + ((z + 8) & 7) * XPL;
        const bool zok = (unsigned)z < (unsigned)D;
        if (zok && intXY) {
            const float* base = xin + z * HW + (y0 - 4) * W + (x0 - 4);
            #pragma unroll
            for (int k = 0; k < 5; ++k) {
                const int r = ty + 8 * k;
                pl[r * 42 + tx] = base[r * W + tx];
                if (tx < 8) pl[r * 42 + 32 + tx] = base[r * W + 32 + tx];
            }
        } else {
            #pragma unroll
            for (int k = 0; k < 5; ++k) {
                const int r = ty + 8 * k;
                const int gy = y0 - 4 + r;
                const bool okY = zok && (unsigned)gy < (unsigned)H;
                const float* rowp = okY ? (xin + z * HW + gy * W) : xin;
                {
                    const int gx = x0 - 4 + tx;
                    pl[r * 42 + tx] =
                        (okY && (unsigned)gx < (unsigned)W) ? rowp[gx] : 0.f;
                }
                if (tx < 8) {
                    const int gx = x0 - 4 + 32 + tx;
                    pl[r * 42 + 32 + tx] =
                        (okY && (unsigned)gx < (unsigned)W) ? rowp[gx] : 0.f;
                }
            }
        }
    };

    // ---- compute E(hn) tile into E ring slot (hn+3)%3 ----
    auto ePlane = [&](int hn) {
        float* Ep = Er + ((hn + 3) % 3) * EPL;
        if ((unsigned)hn >= (unsigned)NS) {
            #pragma unroll
            for (int k = 0; k < 4; ++k) Ep[(ty + 8 * k) * 33 + tx] = 0.f;
            return;
        }
        const int q0 = 2 * hn - 2;
        const float* q0p = xr + ((q0 + 8) & 7) * XPL;
        const float* q1p = xr + ((q0 + 9) & 7) * XPL;
        const float* q2p = xr + ((q0 + 10) & 7) * XPL;
        const float* q3p = xr + ((q0 + 11) & 7) * XPL;
        const float* q4p = xr + ((q0 + 12) & 7) * XPL;
        // S1: z-combine -> sZ (40 x 40)
        #pragma unroll
        for (int k = 0; k < 5; ++k) {
            const int ro = (ty + 8 * k) * 42;
            {
                const int o = ro + tx;
                sZ[o] = p0 * q0p[o] + p1 * q1p[o] + p2 * q2p[o]
                      + p3 * q3p[o] + p4 * q4p[o];
            }
            if (tx < 8) {
                const int o = ro + 32 + tx;
                sZ[o] = p0 * q0p[o] + p1 * q1p[o] + p2 * q2p[o]
                      + p3 * q3p[o] + p4 * q4p[o];
            }
        }
        __syncthreads();
        // S2: x-conv -> sA (40 x 36)
        #pragma unroll
        for (int k = 0; k < 5; ++k) {
            const int r = ty + 8 * k;
            const int ri = r * 42, ro = r * 36;
            sA[ro + tx] = p0 * sZ[ri + tx]     + p1 * sZ[ri + tx + 1]
                        + p2 * sZ[ri + tx + 2] + p3 * sZ[ri + tx + 3]
                        + p4 * sZ[ri + tx + 4];
            if (tx < 4) {
                const int c = 32 + tx;
                sA[ro + c] = p0 * sZ[ri + c]     + p1 * sZ[ri + c + 1]
                           + p2 * sZ[ri + c + 2] + p3 * sZ[ri + c + 3]
                           + p4 * sZ[ri + c + 4];
            }
        }
        __syncthreads();
        // S3: y-conv - slice -> sF (36 x 36, overlays sZ; 0 outside image)
        {
            const float* sl = slices + hn * HW;
            #pragma unroll
            for (int k = 0; k < 5; ++k) {
                const int r = (k < 4) ? (ty + 8 * k) : (32 + ty);
                if (k == 4 && ty >= 4) break;
                const int gy = y0 - 2 + r;
                const bool okY = (unsigned)gy < (unsigned)H;
                #pragma unroll
                for (int b = 0; b < 2; ++b) {
                    if (b == 1 && tx >= 4) break;
                    const int c = b * 32 + tx;
                    const int gx = x0 - 2 + c;
                    float v = 0.f;
                    if (okY && (unsigned)gx < (unsigned)W) {
                        v = p0 * sA[r * 36 + c]       + p1 * sA[(r + 1) * 36 + c]
                          + p2 * sA[(r + 2) * 36 + c] + p3 * sA[(r + 3) * 36 + c]
                          + p4 * sA[(r + 4) * 36 + c] - sl[gy * W + gx];
                    }
                    sF[r * 37 + c] = v;
                }
            }
        }
        __syncthreads();
        // S4: x-conv -> sB (36 x 32, overlays sA)
        #pragma unroll
        for (int k = 0; k < 5; ++k) {
            const int r = (k < 4) ? (ty + 8 * k) : (32 + ty);
            if (k == 4 && ty >= 4) break;
            const int ri = r * 37;
            sB[r * 33 + tx] = p0 * sF[ri + tx]     + p1 * sF[ri + tx + 1]
                            + p2 * sF[ri + tx + 2] + p3 * sF[ri + tx + 3]
                            + p4 * sF[ri + tx + 4];
        }
        __syncthreads();
        // S5: y-conv -> E ring (32 x 32)
        #pragma unroll
        for (int k = 0; k < 4; ++k) {
            const int r = ty + 8 * k;
            Ep[r * 33 + tx] = p0 * sB[r * 33 + tx]       + p1 * sB[(r + 1) * 33 + tx]
                            + p2 * sB[(r + 2) * 33 + tx] + p3 * sB[(r + 3) * 33 + tx]
                            + p4 * sB[(r + 4) * 33 + tx];
        }
    };

    // ---- init: x ring planes zb-4..zb+2, E planes h0-1, h0 ----
    for (int p = zb - 4; p <= zb + 2; ++p) loadPlane(p);
    __syncthreads();
    const int h0 = zb >> 1;
    ePlane(h0 - 1);
    __syncthreads();
    ePlane(h0);
    __syncthreads();

    const float ALPHA = 0.5f;
    const float BETA = (float)(0.02 * 0.1 * 0.1);
    const int gx = x0 + tx;
    const bool ix = (gx > 0) && (gx < W - 1);

    int h = h0;
    for (int z = zb; z < zb + ZC; z += 2, ++h) {
        loadPlane(z + 3);
        loadPlane(z + 4);
        __syncthreads();
        ePlane(h + 1);
        __syncthreads();

        const float* plm = xr + ((z + 7) & 7) * XPL;   // z-1
        const float* pl0 = xr + ((z + 8) & 7) * XPL;   // z
        const float* pl1 = xr + ((z + 9) & 7) * XPL;   // z+1
        const float* pl2 = xr + ((z + 10) & 7) * XPL;  // z+2
        const float* EAp = Er + ((h + 2) % 3) * EPL;   // E(h-1)
        const float* EBp = Er + ((h + 3) % 3) * EPL;   // E(h)
        const float* ECp = Er + ((h + 4) % 3) * EPL;   // E(h+1)

        #pragma unroll
        for (int k = 0; k < 4; ++k) {
            const int r = ty + 8 * k;
            const int gy = y0 + r;
            const bool interior = ix && (gy > 0) && (gy < H - 1);
            const int nb = (r + 3) * 42 + (tx + 3);    // top-left of 3x3

            float Pm[9], P0[9], P1[9], P2[9];
            #pragma unroll
            for (int dy = 0; dy < 3; ++dy)
                #pragma unroll
                for (int dx = 0; dx < 3; ++dx) {
                    const int o = nb + dy * 42 + dx;
                    Pm[dy * 3 + dx] = plm[o];
                    P0[dy * 3 + dx] = pl0[o];
                    P1[dy * 3 + dx] = pl1[o];
                    P2[dy * 3 + dx] = pl2[o];
                }
            const float eA = EAp[r * 33 + tx];
            const float eB = EBp[r * 33 + tx];
            const float eC = ECp[r * 33 + tx];

            float ge = 0.f, go = 0.f;
            if (interior) {
                const unsigned long long v0p  = pk2(P0[4], P1[4]);
                const unsigned long long one2 = pk2(1.0f, 1.0f);
                const unsigned long long m12  = pk2(-1.0f, -1.0f);
                unsigned long long acc = pk2(0.0f, 0.0f);
                #pragma unroll
                for (int j = 0; j < 9; ++j) {
                    const int dy = j / 3 - 1, dx = j % 3 - 1;
                    const int d2 = dy * dy + dx * dx;
                    const float wa = (d2 == 0) ? w1 : ((d2 == 1) ? w2 : w3);
                    {   // dz = -1 : even uses Pm, odd uses P0
                        const unsigned long long np = pk2(Pm[j], P0[j]);
                        const unsigned long long dv = fma2_(np, m12, v0p);
                        const unsigned long long wp = pk2(wa, wa);
                        const unsigned long long t  = mul2_(dv, wp);
                        const unsigned long long ar = fma2_(dv, t, one2);
                        float a0, a1; upk2(ar, a0, a1);
                        acc = fma2_(t, pk2(rsqrtf(a0), rsqrtf(a1)), acc);
                    }
                    {   // dz = +1 : even uses P1, odd uses P2
                        const unsigned long long np = pk2(P1[j], P2[j]);
                        const unsigned long long dv = fma2_(np, m12, v0p);
                        const unsigned long long wp = pk2(wa, wa);
                        const unsigned long long t  = mul2_(dv, wp);
                        const unsigned long long ar = fma2_(dv, t, one2);
                        float a0, a1; upk2(ar, a0, a1);
                        acc = fma2_(t, pk2(rsqrtf(a0), rsqrtf(a1)), acc);
                    }
                    if (j != 4) {  // dz = 0 : even uses P0, odd uses P1
                        const float wb = (d2 == 1) ? w1 : w2;
                        const unsigned long long np = pk2(P0[j], P1[j]);
                        const unsigned long long dv = fma2_(np, m12, v0p);
                        const unsigned long long wp = pk2(wb, wb);
                        const unsigned long long t  = mul2_(dv, wp);
                        const unsigned long long ar = fma2_(dv, t, one2);
                        float a0, a1; upk2(ar, a0, a1);
                        acc = fma2_(t, pk2(rsqrtf(a0), rsqrtf(a1)), acc);
                    }
                }
                upk2(acc, ge, go);
                if (z == 0) ge = 0.f;              // dR zero-padded at z edges
                if (z + 1 == D - 1) go = 0.f;
            }

            const float gde = fmaf(p0, eA, fmaf(p2, eB, p4 * eC));
            const float gdo = fmaf(p1, eB, p3 * eC);
            float xe = P0[4] - ALPHA * (gde + BETA * ge);
            float xo = P1[4] - ALPHA * (gdo + BETA * go);
            if (do_relu) { xe = fmaxf(xe, 0.f); xo = fmaxf(xo, 0.f); }
            const int oidx = gy * W + gx;
            xout[z * HW + oidx] = xe;
            xout[(z + 1) * HW + oidx] = xo;
        }
    }
}

// ===========================================================================
// Generic fallback kernels (runtime dims) — validated in R4/R5.
// ===========================================================================

__global__ __launch_bounds__(256) void fused_E_gen(
    const float* __restrict__ x, const float* __restrict__ slices,
    float* __restrict__ E, const int* __restrict__ stridep,
    int D, int H, int W, int n_slices) {
    __shared__ float sZ[40][44];
    __shared__ float sA[40][36];
    __shared__ float sF[36][36];
    __shared__ float sB[36][33];

    const int i = blockIdx.z;
    const int zi = i * (*stridep);
    const int x0 = blockIdx.x * 32, y0 = blockIdx.y * 32;
    const int tx = threadIdx.x, ty = threadIdx.y;
    const size_t HW = (size_t)H * W;

    const float p0 = d_p[0], p1 = d_p[1], p2 = d_p[2], p3 = d_p[3], p4 = d_p[4];

    {
        const int z0 = zi - 2;
        const bool zok0 = (z0 >= 0), zok1 = (z0 + 1 >= 0);
        const bool zok2 = (z0 + 2 >= 0) && (z0 + 2 < D);
        const bool zok3 = (z0 + 3 < D), zok4 = (z0 + 4 < D);
        #pragma unroll
        for (int k = 0; k < 5; ++k) {
            const int r = ty + 8 * k;
            const int gy = y0 - 4 + r;
            const bool okY = (unsigned)gy < (unsigned)H;
            #pragma unroll
            for (int b = 0; b < 2; ++b) {
                const int c = b * 32 + tx;
                if (b == 1 && tx >= 8) break;
                const int gx = x0 - 4 + c;
                float acc = 0.f;
                if (okY && (unsigned)gx < (unsigned)W) {
                    const float* col = x + (size_t)gy * W + gx + (size_t)z0 * HW;
                    if (zok0) acc = fmaf(p0, col[0], acc);
                    if (zok1) acc = fmaf(p1, col[HW], acc);
                    if (zok2) acc = fmaf(p2, col[2 * HW], acc);
                    if (zok3) acc = fmaf(p3, col[3 * HW], acc);
                    if (zok4) acc = fmaf(p4, col[4 * HW], acc);
                }
                sZ[r][c] = acc;
            }
        }
    }
    __syncthreads();

    #pragma unroll
    for (int k = 0; k < 5; ++k) {
        const int r = ty + 8 * k;
        sA[r][tx] = p0 * sZ[r][tx]     + p1 * sZ[r][tx + 1] + p2 * sZ[r][tx + 2]
                  + p3 * sZ[r][tx + 3] + p4 * sZ[r][tx + 4];
        if (tx < 4) {
            const int c = 32 + tx;
            sA[r][c] = p0 * sZ[r][c]     + p1 * sZ[r][c + 1] + p2 * sZ[r][c + 2]
                     + p3 * sZ[r][c + 3] + p4 * sZ[r][c + 4];
        }
    }
    __syncthreads();

    {
        const float* sl = slices + (size_t)i * HW;
        #pragma unroll
        for (int k = 0; k < 5; ++k) {
            const int r = (k < 4) ? (ty + 8 * k) : (32 + ty);
            if (k == 4 && ty >= 4) break;
            const int gy = y0 - 2 + r;
            const bool okY = (unsigned)gy < (unsigned)H;
            #pragma unroll
            for (int b = 0; b < 2; ++b) {
                const int c = b * 32 + tx;
                if (b == 1 && tx >= 4) break;
                const int gx = x0 - 2 + c;
                float v = 0.f;
                if (okY && (unsigned)gx < (unsigned)W) {
                    v = p0 * sA[r][c]     + p1 * sA[r + 1][c] + p2 * sA[r + 2][c]
                      + p3 * sA[r + 3][c] + p4 * sA[r + 4][c]
                      - sl[(size_t)gy * W + gx];
                }
                sF[r][c] = v;
            }
        }
    }
    __syncthreads();

    #pragma unroll
    for (int k = 0; k < 5; ++k) {
        const int r = (k < 4) ? (ty + 8 * k) : (32 + ty);
        if (k == 4 && ty >= 4) break;
        sB[r][tx] = p0 * sF[r][tx]     + p1 * sF[r][tx + 1] + p2 * sF[r][tx + 2]
                  + p3 * sF[r][tx + 3] + p4 * sF[r][tx + 4];
    }
    __syncthreads();

    {
        float* Ei = E + (size_t)i * HW;
        #pragma unroll
        for (int k = 0; k < 4; ++k) {
            const int r = ty + 8 * k;
            const int gy = y0 + r, gx = x0 + tx;
            if (gy < H && gx < W) {
                Ei[(size_t)gy * W + gx] =
                      p0 * sB[r][tx]     + p1 * sB[r + 1][tx] + p2 * sB[r + 2][tx]
                    + p3 * sB[r + 3][tx] + p4 * sB[r + 4][tx];
            }
        }
    }
}

__global__ __launch_bounds__(256, 4) void update_gen(
    const float* __restrict__ xin, const float* __restrict__ E,
    float* __restrict__ xout, const int* __restrict__ stridep,
    int n_slices, int D, int H, int W, int do_relu) {
    __shared__ float s[3][10][36];

    const int x0 = blockIdx.x * 32, y0 = blockIdx.y * 8;
    const int zb = blockIdx.z * UPD_CHUNK;
    const int tx = threadIdx.x, ty = threadIdx.y;
    const int tid = ty * 32 + tx;
    const size_t HW = (size_t)H * W;
    const int y = y0 + ty, x = x0 + tx;
    const int stride = *stridep;

    const float p0 = d_p[0], p1 = d_p[1], p2 = d_p[2], p3 = d_p[3], p4 = d_p[4];
    const float pz[5] = {p0, p1, p2, p3, p4};
    const float w1 = (float)(1.0 / (1.0 * 0.1 * 0.1));
    const float w2 = (float)(1.0 / (2.0 * 0.1 * 0.1));
    const float w3 = (float)(1.0 / (3.0 * 0.1 * 0.1));

    const int ly0 = tid / 34, lx0 = tid % 34;
    const int gy0 = y0 - 1 + ly0, gx0 = x0 - 1 + lx0;
    const bool ok0 = (unsigned)gy0 < (unsigned)H && (unsigned)gx0 < (unsigned)W;
    const size_t off0 = ok0 ? ((size_t)gy0 * W + gx0) : 0;
    const int i1 = tid + 256;
    const bool has1 = (i1 < 340);
    const int ly1 = has1 ? i1 / 34 : 0, lx1 = has1 ? i1 % 34 : 0;
    const int gy1 = y0 - 1 + ly1, gx1 = x0 - 1 + lx1;
    const bool ok1 = has1 && (unsigned)gy1 < (unsigned)H && (unsigned)gx1 < (unsigned)W;
    const size_t off1 = ok1 ? ((size_t)gy1 * W + gx1) : 0;

    auto loadPlane = [&](int z, int sl) {
        const bool zok = (unsigned)z < (unsigned)D;
        const size_t zo = (size_t)(zok ? z : 0) * HW;
        s[sl][ly0][lx0] = (zok && ok0) ? xin[zo + off0] : 0.f;
        if (has1) s[sl][ly1][lx1] = (zok && ok1) ? xin[zo + off1] : 0.f;
    };

    const int sl_m1 = ((zb - 1) % 3 + 3) % 3;
    const int sl_0  = zb % 3;
    loadPlane(zb - 1, sl_m1);
    loadPlane(zb, sl_0);
    __syncthreads();

    float A[9], B[9];
    #pragma unroll
    for (int dy = 0; dy < 3; ++dy)
        #pragma unroll
        for (int dx = 0; dx < 3; ++dx) {
            A[dy * 3 + dx] = s[sl_m1][ty + dy][tx + dx];
            B[dy * 3 + dx] = s[sl_0][ty + dy][tx + dx];
        }

    const bool interior_xy = (y > 0 && y < H - 1 && x > 0 && x < W - 1);
    const size_t eo = (size_t)y * W + x;
    const float* Ecol = E + eo;
    float* outcol = xout + eo;
    const float ALPHA = 0.5f;
    const float BETA = (float)(0.02 * 0.1 * 0.1);

    int zend = zb + UPD_CHUNK;
    if (zend > D) zend = D;

    for (int z = zb; z < zend; ++z) {
        const int sl = (z + 1) % 3;
        loadPlane(z + 1, sl);
        __syncthreads();

        float C[9];
        #pragma unroll
        for (int dy = 0; dy < 3; ++dy)
            #pragma unroll
            for (int dx = 0; dx < 3; ++dx)
                C[dy * 3 + dx] = s[sl][ty + dy][tx + dx];

        const float v0 = B[4];
        float gd = 0.f;
        #pragma unroll
        for (int dz = 0; dz < 5; ++dz) {
            int zz = z + dz - 2;
            if ((unsigned)zz < (unsigned)D && (zz % stride) == 0) {
                int pi = zz / stride;
                if (pi < n_slices) gd = fmaf(pz[dz], Ecol[(size_t)pi * HW], gd);
            }
        }

        float greg = 0.f;
        if (interior_xy && z > 0 && z < D - 1) {
            #pragma unroll
            for (int j = 0; j < 9; ++j) {
                const int dy = j / 3 - 1, dx = j % 3 - 1;
                const int d2a = dy * dy + dx * dx + 1;
                const float wa = (d2a == 1) ? w1 : ((d2a == 2) ? w2 : w3);
                { float dv = v0 - A[j]; float t = dv * wa; greg += t * rsqrtf(fmaf(dv, t, 1.0f)); }
                { float dv = v0 - C[j]; float t = dv * wa; greg += t * rsqrtf(fmaf(dv, t, 1.0f)); }
                if (j != 4) {
                    const int d2b = dy * dy + dx * dx;
                    const float wb = (d2b == 1) ? w1 : ((d2b == 2) ? w2 : w3);
                    float dv = v0 - B[j]; float t = dv * wb;
                    greg += t * rsqrtf(fmaf(dv, t, 1.0f));
                }
            }
        }

        float xn = v0 - ALPHA * (gd + BETA * greg);
        if (do_relu) xn = fmaxf(xn, 0.f);
        outcol[(size_t)z * HW] = xn;

        #pragma unroll
        for (int j = 0; j < 9; ++j) { A[j] = B[j]; B[j] = C[j]; }
    }
}

// ---------------------------------------------------------------------------
extern "C" void kernel_launch(void* const* d_in, const int* in_sizes, int n_in,
                              void* d_out, int out_size) {
    const float* slices = (const float*)d_in[1];
    const float* volume = (const float*)d_in[2];
    const float* psf    = (const float*)d_in[3];
    const int* stridep  = (const int*)d_in[4];

    int D = (int)lround(cbrt((double)out_size));   // 192
    int H = D, W = D;
    int n_slices = in_sizes[1] / (H * W);

    float *pE, *pA, *pB;
    cudaGetSymbolAddress((void**)&pE, d_E);
    cudaGetSymbolAddress((void**)&pA, d_A);
    cudaGetSymbolAddress((void**)&pB, d_B);

    init_p_kernel<<<1, 32>>>(psf);

    const bool spec = (D == 192 && H == 192 && W == 192 && n_slices == 96);

    if (spec) {
        constexpr int SMB = (8 * 40 * 42 + 3 * 32 * 33 + 40 * 42 + 40 * 36) * 4;
        cudaFuncSetAttribute(mega_t<192, 192, 192, 96, 24>,
                             cudaFuncAttributeMaxDynamicSharedMemorySize, SMB);
        dim3 blk(32, 8, 1);
        dim3 grid(6, 6, 8);
        for (int it = 0; it < N_ITER; ++it) {
            // ping-pong through d_out to keep footprint L2-resident:
            // even it -> pA, odd it -> d_out; it9 lands in d_out.
            const float* xin = (it == 0) ? volume
                                         : ((it & 1) ? pA : (const float*)d_out);
            float* xout = (it & 1) ? (float*)d_out : pA;
            int do_relu = (it == N_ITER - 1) ? 1 : 0;
            mega_t<192, 192, 192, 96, 24><<<grid, blk, SMB>>>(
                xin, slices, xout, stridep, do_relu);
        }
    } else {
        dim3 blkE(32, 8, 1);
        dim3 grid_E((W + 31) / 32, (H + 31) / 32, n_slices);
        dim3 blkU(32, 8, 1);
        dim3 grid_up((W + 31) / 32, (H + 7) / 8, (D + UPD_CHUNK - 1) / UPD_CHUNK);
        for (int it = 0; it < N_ITER; ++it) {
            const float* xin = (it == 0) ? volume : ((it & 1) ? pA : pB);
            float* xout = (it == N_ITER - 1) ? (float*)d_out
                                             : ((it & 1) ? pB : pA);
            int do_relu = (it == N_ITER - 1) ? 1 : 0;
            fused_E_gen<<<grid_E, blkE>>>(xin, slices, pE, stridep, D, H, W, n_slices);
            update_gen<<<grid_up, blkU>>>(xin, pE, xout, stridep, n_slices, D, H, W, do_relu);
        }
    }
}

// round 11
// speedup vs baseline: 1.4107x; 1.4107x over previous
#include <cuda_runtime.h>
#include <math.h>

#define N_ITER 10
#define UPD_CHUNK 24

static __device__ float d_p[5];                     // separable 1D psf
static __device__ float d_E[96 * 192 * 192];        // conv_xy(residual) planes
static __device__ float d_A[192 * 192 * 192];       // ping
static __device__ float d_B[192 * 192 * 192];       // generic path pong

// ---------------------------------------------------------------------------
// packed f32x2 helpers (Blackwell)
// ---------------------------------------------------------------------------
__device__ __forceinline__ unsigned long long pk2(float lo, float hi) {
    unsigned long long r;
    asm("mov.b64 %0, {%1, %2};" : "=l"(r) : "f"(lo), "f"(hi));
    return r;
}
__device__ __forceinline__ void upk2(unsigned long long v, float& lo, float& hi) {
    asm("mov.b64 {%0, %1}, %2;" : "=f"(lo), "=f"(hi) : "l"(v));
}
__device__ __forceinline__ unsigned long long fma2_(unsigned long long a,
                                                    unsigned long long b,
                                                    unsigned long long c) {
    unsigned long long d;
    asm("fma.rn.f32x2 %0, %1, %2, %3;" : "=l"(d) : "l"(a), "l"(b), "l"(c));
    return d;
}
__device__ __forceinline__ unsigned long long mul2_(unsigned long long a,
                                                    unsigned long long b) {
    unsigned long long d;
    asm("mul.rn.f32x2 %0, %1, %2;" : "=l"(d) : "l"(a), "l"(b));
    return d;
}

// ---------------------------------------------------------------------------
__global__ void init_p_kernel(const float* __restrict__ psf) {
    int i = threadIdx.x;
    if (i < 5) {
        float s = 0.f;
        for (int j = 0; j < 25; ++j) s += psf[i * 25 + j];
        d_p[i] = s;
    }
}

// ===========================================================================
// Specialized kernels: compile-time D,H,W,NS (192,192,192,96); int offsets.
// (Structure identical to the R7 kernels benched at 1113.4 us.)
// ===========================================================================

template <int D, int H, int W, int NS>
__global__ __launch_bounds__(256, 5) void fused_E2_t(
    const float* __restrict__ x, const float* __restrict__ slices,
    float* __restrict__ E, const int* __restrict__ stridep) {
    constexpr int HW = H * W;
    __shared__ float bufZ[2][40][42];   // stage1 out; later overlaid by sF (36x37)
    __shared__ float bufA[2][40][36];   // stage2 out; later overlaid by sB (36x33)

    const int pr = blockIdx.z;
    const int stride = *stridep;
    const int iA = 2 * pr;
    const int ziA = iA * stride;
    const int x0 = blockIdx.x * 32, y0 = blockIdx.y * 32;
    const int tx = threadIdx.x, ty = threadIdx.y;

    const float p0 = d_p[0], p1 = d_p[1], p2 = d_p[2], p3 = d_p[3], p4 = d_p[4];

    const bool intXY = (x0 >= 4) && (x0 + 36 <= W) && (y0 >= 4) && (y0 + 36 <= H);

    // ---- stage 1: z-combine both slices ----
    if (stride == 2) {
        const int q0 = ziA - 2;                  // planes q0 .. q0+6
        const bool intZ = (q0 >= 0) && (ziA + 4 < D);
        if (intZ && intXY) {
            const float* base = x + q0 * HW + (y0 - 4) * W + (x0 - 4);
            #pragma unroll
            for (int k = 0; k < 5; ++k) {
                const int r = ty + 8 * k;
                const float* rowp = base + r * W;
                #pragma unroll
                for (int b = 0; b < 2; ++b) {
                    if (b == 1 && tx >= 8) break;
                    const int c = b * 32 + tx;
                    const float* col = rowp + c;
                    const float v0 = col[0],      v1 = col[HW],     v2 = col[2 * HW];
                    const float v3 = col[3 * HW], v4 = col[4 * HW], v5 = col[5 * HW];
                    const float v6 = col[6 * HW];
                    bufZ[0][r][c] = p0 * v0 + p1 * v1 + p2 * v2 + p3 * v3 + p4 * v4;
                    bufZ[1][r][c] = p0 * v2 + p1 * v3 + p2 * v4 + p3 * v5 + p4 * v6;
                }
            }
        } else {
            bool qok[7];
            #pragma unroll
            for (int j = 0; j < 7; ++j) qok[j] = (unsigned)(q0 + j) < (unsigned)D;
            #pragma unroll
            for (int k = 0; k < 5; ++k) {
                const int r = ty + 8 * k;
                const int gy = y0 - 4 + r;
                const bool okY = (unsigned)gy < (unsigned)H;
                #pragma unroll
                for (int b = 0; b < 2; ++b) {
                    if (b == 1 && tx >= 8) break;
                    const int c = b * 32 + tx;
                    const int gx = x0 - 4 + c;
                    const bool okXY = okY && (unsigned)gx < (unsigned)W;
                    const float* col = x + gy * W + gx;
                    float v[7];
                    #pragma unroll
                    for (int j = 0; j < 7; ++j)
                        v[j] = (okXY && qok[j]) ? col[(q0 + j) * HW] : 0.f;
                    bufZ[0][r][c] = p0 * v[0] + p1 * v[1] + p2 * v[2] + p3 * v[3] + p4 * v[4];
                    bufZ[1][r][c] = p0 * v[2] + p1 * v[3] + p2 * v[4] + p3 * v[5] + p4 * v[6];
                }
            }
        }
    } else {
        #pragma unroll
        for (int s = 0; s < 2; ++s) {
            const int zi = (iA + s) * stride;
            const int z0 = zi - 2;
            bool zok[5];
            #pragma unroll
            for (int j = 0; j < 5; ++j) zok[j] = (unsigned)(z0 + j) < (unsigned)D;
            #pragma unroll
            for (int k = 0; k < 5; ++k) {
                const int r = ty + 8 * k;
                const int gy = y0 - 4 + r;
                const bool okY = (unsigned)gy < (unsigned)H;
                #pragma unroll
                for (int b = 0; b < 2; ++b) {
                    if (b == 1 && tx >= 8) break;
                    const int c = b * 32 + tx;
                    const int gx = x0 - 4 + c;
                    const bool okXY = okY && (unsigned)gx < (unsigned)W;
                    const float* col = x + gy * W + gx;
                    float acc = 0.f;
                    if (okXY) {
                        if (zok[0]) acc = fmaf(p0, col[(z0 + 0) * HW], acc);
                        if (zok[1]) acc = fmaf(p1, col[(z0 + 1) * HW], acc);
                        if (zok[2]) acc = fmaf(p2, col[(z0 + 2) * HW], acc);
                        if (zok[3]) acc = fmaf(p3, col[(z0 + 3) * HW], acc);
                        if (zok[4]) acc = fmaf(p4, col[(z0 + 4) * HW], acc);
                    }
                    bufZ[s][r][c] = acc;
                }
            }
        }
    }
    __syncthreads();

    // ---- stage 2: x-conv into bufA (40 x 36) ----
    #pragma unroll
    for (int s = 0; s < 2; ++s) {
        #pragma unroll
        for (int k = 0; k < 5; ++k) {
            const int r = ty + 8 * k;
            bufA[s][r][tx] = p0 * bufZ[s][r][tx]     + p1 * bufZ[s][r][tx + 1]
                           + p2 * bufZ[s][r][tx + 2] + p3 * bufZ[s][r][tx + 3]
                           + p4 * bufZ[s][r][tx + 4];
            if (tx < 4) {
                const int c = 32 + tx;
                bufA[s][r][c] = p0 * bufZ[s][r][c]     + p1 * bufZ[s][r][c + 1]
                              + p2 * bufZ[s][r][c + 2] + p3 * bufZ[s][r][c + 3]
                              + p4 * bufZ[s][r][c + 4];
            }
        }
    }
    __syncthreads();

    // ---- stage 3: y-conv + subtract slice into sF (36 x 36, overlays bufZ) ----
    {
        float (*sF0)[37] = (float (*)[37]) &bufZ[0][0][0];
        float (*sF1)[37] = (float (*)[37]) &bufZ[1][0][0];
        #pragma unroll
        for (int s = 0; s < 2; ++s) {
            float (*sF)[37] = s ? sF1 : sF0;
            const float* sl = slices + (iA + s) * HW;
            if (intXY) {
                const float* sbase = sl + (y0 - 2) * W + (x0 - 2);
                #pragma unroll
                for (int k = 0; k < 5; ++k) {
                    const int r = (k < 4) ? (ty + 8 * k) : (32 + ty);
                    if (k == 4 && ty >= 4) break;
                    sF[r][tx] = p0 * bufA[s][r][tx]     + p1 * bufA[s][r + 1][tx]
                              + p2 * bufA[s][r + 2][tx] + p3 * bufA[s][r + 3][tx]
                              + p4 * bufA[s][r + 4][tx] - sbase[r * W + tx];
                    if (tx < 4) {
                        const int c = 32 + tx;
                        sF[r][c] = p0 * bufA[s][r][c]     + p1 * bufA[s][r + 1][c]
                                 + p2 * bufA[s][r + 2][c] + p3 * bufA[s][r + 3][c]
                                 + p4 * bufA[s][r + 4][c] - sbase[r * W + c];
                    }
                }
            } else {
                #pragma unroll
                for (int k = 0; k < 5; ++k) {
                    const int r = (k < 4) ? (ty + 8 * k) : (32 + ty);
                    if (k == 4 && ty >= 4) break;
                    const int gy = y0 - 2 + r;
                    const bool okY = (unsigned)gy < (unsigned)H;
                    #pragma unroll
                    for (int b = 0; b < 2; ++b) {
                        if (b == 1 && tx >= 4) break;
                        const int c = b * 32 + tx;
                        const int gx = x0 - 2 + c;
                        float v = 0.f;
                        if (okY && (unsigned)gx < (unsigned)W) {
                            v = p0 * bufA[s][r][c]     + p1 * bufA[s][r + 1][c]
                              + p2 * bufA[s][r + 2][c] + p3 * bufA[s][r + 3][c]
                              + p4 * bufA[s][r + 4][c] - sl[gy * W + gx];
                        }
                        sF[r][c] = v;
                    }
                }
            }
        }
    }
    __syncthreads();

    // ---- stage 4: x-conv into sB (36 x 32, overlays bufA) ----
    {
        float (*sF0)[37] = (float (*)[37]) &bufZ[0][0][0];
        float (*sF1)[37] = (float (*)[37]) &bufZ[1][0][0];
        float (*sB0)[33] = (float (*)[33]) &bufA[0][0][0];
        float (*sB1)[33] = (float (*)[33]) &bufA[1][0][0];
        #pragma unroll
        for (int s = 0; s < 2; ++s) {
            float (*sF)[37] = s ? sF1 : sF0;
            float (*sB)[33] = s ? sB1 : sB0;
            #pragma unroll
            for (int k = 0; k < 5; ++k) {
                const int r = (k < 4) ? (ty + 8 * k) : (32 + ty);
                if (k == 4 && ty >= 4) break;
                sB[r][tx] = p0 * sF[r][tx]     + p1 * sF[r][tx + 1] + p2 * sF[r][tx + 2]
                          + p3 * sF[r][tx + 3] + p4 * sF[r][tx + 4];
            }
        }
    }
    __syncthreads();

    // ---- stage 5: y-conv, store E (32 x 32 each) ----
    {
        float (*sB0)[33] = (float (*)[33]) &bufA[0][0][0];
        float (*sB1)[33] = (float (*)[33]) &bufA[1][0][0];
        #pragma unroll
        for (int s = 0; s < 2; ++s) {
            float (*sB)[33] = s ? sB1 : sB0;
            float* Ei = E + (iA + s) * HW + y0 * W + x0;
            #pragma unroll
            for (int k = 0; k < 4; ++k) {
                const int r = ty + 8 * k;
                Ei[r * W + tx] = p0 * sB[r][tx]     + p1 * sB[r + 1][tx]
                               + p2 * sB[r + 2][tx] + p3 * sB[r + 3][tx]
                               + p4 * sB[r + 4][tx];
            }
        }
    }
}

// ---------------------------------------------------------------------------
// update: 2 z per barrier, packed f32x2 regularizer for the voxel pair.
template <int D, int H, int W, int NS>
__global__ __launch_bounds__(256, 4) void update2_t(
    const float* __restrict__ xin, const float* __restrict__ E,
    float* __restrict__ xout, const int* __restrict__ stridep, int do_relu) {
    constexpr int HW = H * W;
    __shared__ float s[4][10][36];

    const int x0 = blockIdx.x * 32, y0 = blockIdx.y * 8;
    const int zb = blockIdx.z * UPD_CHUNK;        // even
    const int tx = threadIdx.x, ty = threadIdx.y;
    const int tid = ty * 32 + tx;
    const int y = y0 + ty, x = x0 + tx;
    const int stride = *stridep;

    const float p0 = d_p[0], p1 = d_p[1], p2 = d_p[2], p3 = d_p[3], p4 = d_p[4];

    const float w1 = (float)(1.0 / (1.0 * 0.1 * 0.1));
    const float w2 = (float)(1.0 / (2.0 * 0.1 * 0.1));
    const float w3 = (float)(1.0 / (3.0 * 0.1 * 0.1));

    // hoisted cooperative-load geometry (10*34 = 340 slots)
    const int ly0 = tid / 34, lx0 = tid % 34;
    const int gy0 = y0 - 1 + ly0, gx0 = x0 - 1 + lx0;
    const bool ok0 = (unsigned)gy0 < (unsigned)H && (unsigned)gx0 < (unsigned)W;
    const int off0 = ok0 ? (gy0 * W + gx0) : 0;

    const int i1 = tid + 256;
    const bool has1 = (i1 < 340);
    const int ly1 = has1 ? i1 / 34 : 0, lx1 = has1 ? i1 % 34 : 0;
    const int gy1 = y0 - 1 + ly1, gx1 = x0 - 1 + lx1;
    const bool ok1 = has1 && (unsigned)gy1 < (unsigned)H && (unsigned)gx1 < (unsigned)W;
    const int off1 = ok1 ? (gy1 * W + gx1) : 0;

    auto loadPlane = [&](int z, int sl) {
        const bool zok = (unsigned)z < (unsigned)D;
        const int zo = (zok ? z : 0) * HW;
        s[sl][ly0][lx0] = (zok && ok0) ? xin[zo + off0] : 0.f;
        if (has1) s[sl][ly1][lx1] = (zok && ok1) ? xin[zo + off1] : 0.f;
    };

    loadPlane(zb - 1, (zb - 1) & 3);
    loadPlane(zb, zb & 3);
    __syncthreads();

    float A[9], B[9];
    {
        const int sm = (zb - 1) & 3, s0 = zb & 3;
        #pragma unroll
        for (int dy = 0; dy < 3; ++dy)
            #pragma unroll
            for (int dx = 0; dx < 3; ++dx) {
                A[dy * 3 + dx] = s[sm][ty + dy][tx + dx];
                B[dy * 3 + dx] = s[s0][ty + dy][tx + dx];
            }
    }

    const bool interior_xy = (y > 0 && y < H - 1 && x > 0 && x < W - 1);
    const int eo = y * W + x;
    const float* Ecol = E + eo;
    float* outcol = xout + eo;
    const float ALPHA = 0.5f;
    const float BETA = (float)(0.02 * 0.1 * 0.1);

    auto regTerm = [&](const float* Av, const float* Bv, const float* Cv) -> float {
        float greg = 0.f;
        const float v0 = Bv[4];
        #pragma unroll
        for (int j = 0; j < 9; ++j) {
            const int dy = j / 3 - 1, dx = j % 3 - 1;
            const int d2a = dy * dy + dx * dx + 1;
            const float wa = (d2a == 1) ? w1 : ((d2a == 2) ? w2 : w3);
            { float dv = v0 - Av[j]; float t = dv * wa; greg += t * rsqrtf(fmaf(dv, t, 1.0f)); }
            { float dv = v0 - Cv[j]; float t = dv * wa; greg += t * rsqrtf(fmaf(dv, t, 1.0f)); }
            if (j != 4) {
                const int d2b = dy * dy + dx * dx;
                const float wb = (d2b == 1) ? w1 : ((d2b == 2) ? w2 : w3);
                float dv = v0 - Bv[j]; float t = dv * wb;
                greg += t * rsqrtf(fmaf(dv, t, 1.0f));
            }
        }
        return greg;
    };

    const int zend = (zb + UPD_CHUNK < D) ? (zb + UPD_CHUNK) : D;

    if (stride == 2) {
        int h = zb >> 1;
        float eA = (h >= 1) ? Ecol[(h - 1) * HW] : 0.f;
        float eB = (h < NS) ? Ecol[h * HW] : 0.f;
        float eC = (h + 1 < NS) ? Ecol[(h + 1) * HW] : 0.f;

        for (int z = zb; z < zend; z += 2, ++h) {
            const int s1 = (z + 1) & 3, s2 = (z + 2) & 3;
            loadPlane(z + 1, s1);
            loadPlane(z + 2, s2);
            __syncthreads();

            float C1[9], C2[9];
            #pragma unroll
            for (int dy = 0; dy < 3; ++dy)
                #pragma unroll
                for (int dx = 0; dx < 3; ++dx) {
                    C1[dy * 3 + dx] = s[s1][ty + dy][tx + dx];
                    C2[dy * 3 + dx] = s[s2][ty + dy][tx + dx];
                }

            // ---- packed f32x2 regularizer for voxel pair (z, z+1) ----
            float ge = 0.f, go = 0.f;
            if (interior_xy) {
                const unsigned long long v0p  = pk2(B[4], C1[4]);
                const unsigned long long one2 = pk2(1.0f, 1.0f);
                const unsigned long long m12  = pk2(-1.0f, -1.0f);
                unsigned long long acc = pk2(0.0f, 0.0f);

                #pragma unroll
                for (int j = 0; j < 9; ++j) {
                    const int dy = j / 3 - 1, dx = j % 3 - 1;
                    const int d2 = dy * dy + dx * dx;
                    const float wa = (d2 == 0) ? w1 : ((d2 == 1) ? w2 : w3); // dz=+-1
                    {
                        const unsigned long long np = pk2(A[j], B[j]);
                        const unsigned long long dv = fma2_(np, m12, v0p);
                        const unsigned long long wp = pk2(wa, wa);
                        const unsigned long long t  = mul2_(dv, wp);
                        const unsigned long long ar = fma2_(dv, t, one2);
                        float a0, a1; upk2(ar, a0, a1);
                        acc = fma2_(t, pk2(rsqrtf(a0), rsqrtf(a1)), acc);
                    }
                    {
                        const unsigned long long np = pk2(C1[j], C2[j]);
                        const unsigned long long dv = fma2_(np, m12, v0p);
                        const unsigned long long wp = pk2(wa, wa);
                        const unsigned long long t  = mul2_(dv, wp);
                        const unsigned long long ar = fma2_(dv, t, one2);
                        float a0, a1; upk2(ar, a0, a1);
                        acc = fma2_(t, pk2(rsqrtf(a0), rsqrtf(a1)), acc);
                    }
                    if (j != 4) {
                        const float wb = (d2 == 1) ? w1 : w2;
                        const unsigned long long np = pk2(B[j], C1[j]);
                        const unsigned long long dv = fma2_(np, m12, v0p);
                        const unsigned long long wp = pk2(wb, wb);
                        const unsigned long long t  = mul2_(dv, wp);
                        const unsigned long long ar = fma2_(dv, t, one2);
                        float a0, a1; upk2(ar, a0, a1);
                        acc = fma2_(t, pk2(rsqrtf(a0), rsqrtf(a1)), acc);
                    }
                }
                upk2(acc, ge, go);
                if (z == 0) ge = 0.f;                  // dR zero-padded at z edges
                if (z + 1 == D - 1) go = 0.f;
            }

            // ---- even z ----
            {
                float gd = fmaf(p0, eA, fmaf(p2, eB, p4 * eC));
                float xn = B[4] - ALPHA * (gd + BETA * ge);
                if (do_relu) xn = fmaxf(xn, 0.f);
                outcol[z * HW] = xn;
            }
            // ---- odd z+1 ----
            {
                float gd = fmaf(p1, eB, p3 * eC);
                float xn = C1[4] - ALPHA * (gd + BETA * go);
                if (do_relu) xn = fmaxf(xn, 0.f);
                outcol[(z + 1) * HW] = xn;
            }

            #pragma unroll
            for (int j = 0; j < 9; ++j) { A[j] = C1[j]; B[j] = C2[j]; }
            eA = eB; eB = eC;
            eC = (h + 2 < NS) ? Ecol[(h + 2) * HW] : 0.f;
        }
    } else {
        const float pz[5] = {p0, p1, p2, p3, p4};
        for (int z = zb; z < zend; ++z) {
            const int sl = (z + 1) & 3;
            loadPlane(z + 1, sl);
            __syncthreads();
            float C[9];
            #pragma unroll
            for (int dy = 0; dy < 3; ++dy)
                #pragma unroll
                for (int dx = 0; dx < 3; ++dx)
                    C[dy * 3 + dx] = s[sl][ty + dy][tx + dx];

            float gd = 0.f;
            #pragma unroll
            for (int dz = 0; dz < 5; ++dz) {
                int zz = z + dz - 2;
                if ((unsigned)zz < (unsigned)D && (zz % stride) == 0) {
                    int pi = zz / stride;
                    if (pi < NS) gd = fmaf(pz[dz], Ecol[pi * HW], gd);
                }
            }
            float greg = 0.f;
            if (interior_xy && z > 0 && z < D - 1) greg = regTerm(A, B, C);
            float xn = B[4] - ALPHA * (gd + BETA * greg);
            if (do_relu) xn = fmaxf(xn, 0.f);
            outcol[z * HW] = xn;
            #pragma unroll
            for (int j = 0; j < 9; ++j) { A[j] = B[j]; B[j] = C[j]; }
        }
    }
}

// ===========================================================================
// Generic fallback kernels (runtime dims) — validated in R4/R5.
// ===========================================================================

__global__ __launch_bounds__(256) void fused_E_gen(
    const float* __restrict__ x, const float* __restrict__ slices,
    float* __restrict__ E, const int* __restrict__ stridep,
    int D, int H, int W, int n_slices) {
    __shared__ float sZ[40][44];
    __shared__ float sA[40][36];
    __shared__ float sF[36][36];
    __shared__ float sB[36][33];

    const int i = blockIdx.z;
    const int zi = i * (*stridep);
    const int x0 = blockIdx.x * 32, y0 = blockIdx.y * 32;
    const int tx = threadIdx.x, ty = threadIdx.y;
    const size_t HW = (size_t)H * W;

    const float p0 = d_p[0], p1 = d_p[1], p2 = d_p[2], p3 = d_p[3], p4 = d_p[4];

    {
        const int z0 = zi - 2;
        const bool zok0 = (z0 >= 0), zok1 = (z0 + 1 >= 0);
        const bool zok2 = (z0 + 2 >= 0) && (z0 + 2 < D);
        const bool zok3 = (z0 + 3 < D), zok4 = (z0 + 4 < D);
        #pragma unroll
        for (int k = 0; k < 5; ++k) {
            const int r = ty + 8 * k;
            const int gy = y0 - 4 + r;
            const bool okY = (unsigned)gy < (unsigned)H;
            #pragma unroll
            for (int b = 0; b < 2; ++b) {
                const int c = b * 32 + tx;
                if (b == 1 && tx >= 8) break;
                const int gx = x0 - 4 + c;
                float acc = 0.f;
                if (okY && (unsigned)gx < (unsigned)W) {
                    const float* col = x + (size_t)gy * W + gx + (size_t)z0 * HW;
                    if (zok0) acc = fmaf(p0, col[0], acc);
                    if (zok1) acc = fmaf(p1, col[HW], acc);
                    if (zok2) acc = fmaf(p2, col[2 * HW], acc);
                    if (zok3) acc = fmaf(p3, col[3 * HW], acc);
                    if (zok4) acc = fmaf(p4, col[4 * HW], acc);
                }
                sZ[r][c] = acc;
            }
        }
    }
    __syncthreads();

    #pragma unroll
    for (int k = 0; k < 5; ++k) {
        const int r = ty + 8 * k;
        sA[r][tx] = p0 * sZ[r][tx]     + p1 * sZ[r][tx + 1] + p2 * sZ[r][tx + 2]
                  + p3 * sZ[r][tx + 3] + p4 * sZ[r][tx + 4];
        if (tx < 4) {
            const int c = 32 + tx;
            sA[r][c] = p0 * sZ[r][c]     + p1 * sZ[r][c + 1] + p2 * sZ[r][c + 2]
                     + p3 * sZ[r][c + 3] + p4 * sZ[r][c + 4];
        }
    }
    __syncthreads();

    {
        const float* sl = slices + (size_t)i * HW;
        #pragma unroll
        for (int k = 0; k < 5; ++k) {
            const int r = (k < 4) ? (ty + 8 * k) : (32 + ty);
            if (k == 4 && ty >= 4) break;
            const int gy = y0 - 2 + r;
            const bool okY = (unsigned)gy < (unsigned)H;
            #pragma unroll
            for (int b = 0; b < 2; ++b) {
                const int c = b * 32 + tx;
                if (b == 1 && tx >= 4) break;
                const int gx = x0 - 2 + c;
                float v = 0.f;
                if (okY && (unsigned)gx < (unsigned)W) {
                    v = p0 * sA[r][c]     + p1 * sA[r + 1][c] + p2 * sA[r + 2][c]
                      + p3 * sA[r + 3][c] + p4 * sA[r + 4][c]
                      - sl[(size_t)gy * W + gx];
                }
                sF[r][c] = v;
            }
        }
    }
    __syncthreads();

    #pragma unroll
    for (int k = 0; k < 5; ++k) {
        const int r = (k < 4) ? (ty + 8 * k) : (32 + ty);
        if (k == 4 && ty >= 4) break;
        sB[r][tx] = p0 * sF[r][tx]     + p1 * sF[r][tx + 1] + p2 * sF[r][tx + 2]
                  + p3 * sF[r][tx + 3] + p4 * sF[r][tx + 4];
    }
    __syncthreads();

    {
        float* Ei = E + (size_t)i * HW;
        #pragma unroll
        for (int k = 0; k < 4; ++k) {
            const int r = ty + 8 * k;
            const int gy = y0 + r, gx = x0 + tx;
            if (gy < H && gx < W) {
                Ei[(size_t)gy * W + gx] =
                      p0 * sB[r][tx]     + p1 * sB[r + 1][tx] + p2 * sB[r + 2][tx]
                    + p3 * sB[r + 3][tx] + p4 * sB[r + 4][tx];
            }
        }
    }
}

__global__ __launch_bounds__(256, 4) void update_gen(
    const float* __restrict__ xin, const float* __restrict__ E,
    float* __restrict__ xout, const int* __restrict__ stridep,
    int n_slices, int D, int H, int W, int do_relu) {
    __shared__ float s[3][10][36];

    const int x0 = blockIdx.x * 32, y0 = blockIdx.y * 8;
    const int zb = blockIdx.z * UPD_CHUNK;
    const int tx = threadIdx.x, ty = threadIdx.y;
    const int tid = ty * 32 + tx;
    const size_t HW = (size_t)H * W;
    const int y = y0 + ty, x = x0 + tx;
    const int stride = *stridep;

    const float p0 = d_p[0], p1 = d_p[1], p2 = d_p[2], p3 = d_p[3], p4 = d_p[4];
    const float pz[5] = {p0, p1, p2, p3, p4};
    const float w1 = (float)(1.0 / (1.0 * 0.1 * 0.1));
    const float w2 = (float)(1.0 / (2.0 * 0.1 * 0.1));
    const float w3 = (float)(1.0 / (3.0 * 0.1 * 0.1));

    const int ly0 = tid / 34, lx0 = tid % 34;
    const int gy0 = y0 - 1 + ly0, gx0 = x0 - 1 + lx0;
    const bool ok0 = (unsigned)gy0 < (unsigned)H && (unsigned)gx0 < (unsigned)W;
    const size_t off0 = ok0 ? ((size_t)gy0 * W + gx0) : 0;
    const int i1 = tid + 256;
    const bool has1 = (i1 < 340);
    const int ly1 = has1 ? i1 / 34 : 0, lx1 = has1 ? i1 % 34 : 0;
    const int gy1 = y0 - 1 + ly1, gx1 = x0 - 1 + lx1;
    const bool ok1 = has1 && (unsigned)gy1 < (unsigned)H && (unsigned)gx1 < (unsigned)W;
    const size_t off1 = ok1 ? ((size_t)gy1 * W + gx1) : 0;

    auto loadPlane = [&](int z, int sl) {
        const bool zok = (unsigned)z < (unsigned)D;
        const size_t zo = (size_t)(zok ? z : 0) * HW;
        s[sl][ly0][lx0] = (zok && ok0) ? xin[zo + off0] : 0.f;
        if (has1) s[sl][ly1][lx1] = (zok && ok1) ? xin[zo + off1] : 0.f;
    };

    const int sl_m1 = ((zb - 1) % 3 + 3) % 3;
    const int sl_0  = zb % 3;
    loadPlane(zb - 1, sl_m1);
    loadPlane(zb, sl_0);
    __syncthreads();

    float A[9], B[9];
    #pragma unroll
    for (int dy = 0; dy < 3; ++dy)
        #pragma unroll
        for (int dx = 0; dx < 3; ++dx) {
            A[dy * 3 + dx] = s[sl_m1][ty + dy][tx + dx];
            B[dy * 3 + dx] = s[sl_0][ty + dy][tx + dx];
        }

    const bool interior_xy = (y > 0 && y < H - 1 && x > 0 && x < W - 1);
    const size_t eo = (size_t)y * W + x;
    const float* Ecol = E + eo;
    float* outcol = xout + eo;
    const float ALPHA = 0.5f;
    const float BETA = (float)(0.02 * 0.1 * 0.1);

    int zend = zb + UPD_CHUNK;
    if (zend > D) zend = D;

    for (int z = zb; z < zend; ++z) {
        const int sl = (z + 1) % 3;
        loadPlane(z + 1, sl);
        __syncthreads();

        float C[9];
        #pragma unroll
        for (int dy = 0; dy < 3; ++dy)
            #pragma unroll
            for (int dx = 0; dx < 3; ++dx)
                C[dy * 3 + dx] = s[sl][ty + dy][tx + dx];

        const float v0 = B[4];
        float gd = 0.f;
        #pragma unroll
        for (int dz = 0; dz < 5; ++dz) {
            int zz = z + dz - 2;
            if ((unsigned)zz < (unsigned)D && (zz % stride) == 0) {
                int pi = zz / stride;
                if (pi < n_slices) gd = fmaf(pz[dz], Ecol[(size_t)pi * HW], gd);
            }
        }

        float greg = 0.f;
        if (interior_xy && z > 0 && z < D - 1) {
            #pragma unroll
            for (int j = 0; j < 9; ++j) {
                const int dy = j / 3 - 1, dx = j % 3 - 1;
                const int d2a = dy * dy + dx * dx + 1;
                const float wa = (d2a == 1) ? w1 : ((d2a == 2) ? w2 : w3);
                { float dv = v0 - A[j]; float t = dv * wa; greg += t * rsqrtf(fmaf(dv, t, 1.0f)); }
                { float dv = v0 - C[j]; float t = dv * wa; greg += t * rsqrtf(fmaf(dv, t, 1.0f)); }
                if (j != 4) {
                    const int d2b = dy * dy + dx * dx;
                    const float wb = (d2b == 1) ? w1 : ((d2b == 2) ? w2 : w3);
                    float dv = v0 - B[j]; float t = dv * wb;
                    greg += t * rsqrtf(fmaf(dv, t, 1.0f));
                }
            }
        }

        float xn = v0 - ALPHA * (gd + BETA * greg);
        if (do_relu) xn = fmaxf(xn, 0.f);
        outcol[(size_t)z * HW] = xn;

        #pragma unroll
        for (int j = 0; j < 9; ++j) { A[j] = B[j]; B[j] = C[j]; }
    }
}

// ---------------------------------------------------------------------------
extern "C" void kernel_launch(void* const* d_in, const int* in_sizes, int n_in,
                              void* d_out, int out_size) {
    const float* slices = (const float*)d_in[1];
    const float* volume = (const float*)d_in[2];
    const float* psf    = (const float*)d_in[3];
    const int* stridep  = (const int*)d_in[4];

    int D = (int)lround(cbrt((double)out_size));   // 192
    int H = D, W = D;
    int n_slices = in_sizes[1] / (H * W);

    float *pE, *pA, *pB;
    cudaGetSymbolAddress((void**)&pE, d_E);
    cudaGetSymbolAddress((void**)&pA, d_A);
    cudaGetSymbolAddress((void**)&pB, d_B);

    init_p_kernel<<<1, 32>>>(psf);

    const bool spec = (D == 192 && H == 192 && W == 192 && n_slices == 96);

    dim3 blkE(32, 8, 1);
    dim3 grid_E2((W + 31) / 32, (H + 31) / 32, n_slices / 2);
    dim3 grid_E((W + 31) / 32, (H + 31) / 32, n_slices);
    dim3 blkU(32, 8, 1);
    dim3 grid_up((W + 31) / 32, (H + 7) / 8, (D + UPD_CHUNK - 1) / UPD_CHUNK);

    if (spec) {
        for (int it = 0; it < N_ITER; ++it) {
            // L2-fit: ping-pong through d_out (no pong buffer).
            // even it -> writes pA, odd it -> writes d_out; it9 (odd) -> d_out.
            const float* xin = (it == 0) ? volume
                                         : ((it & 1) ? pA : (const float*)d_out);
            float* xout = (it & 1) ? (float*)d_out : pA;
            int do_relu = (it == N_ITER - 1) ? 1 : 0;
            fused_E2_t<192, 192, 192, 96><<<grid_E2, blkE>>>(xin, slices, pE, stridep);
            update2_t<192, 192, 192, 96><<<grid_up, blkU>>>(xin, pE, xout, stridep, do_relu);
        }
    } else {
        for (int it = 0; it < N_ITER; ++it) {
            const float* xin = (it == 0) ? volume : ((it & 1) ? pA : pB);
            float* xout = (it == N_ITER - 1) ? (float*)d_out
                                             : ((it & 1) ? pB : pA);
            int do_relu = (it == N_ITER - 1) ? 1 : 0;
            fused_E_gen<<<grid_E, blkE>>>(xin, slices, pE, stridep, D, H, W, n_slices);
            update_gen<<<grid_up, blkU>>>(xin, pE, xout, stridep, n_slices, D, H, W, do_relu);
        }
    }
}

// round 12
// speedup vs baseline: 1.4990x; 1.0626x over previous
#include <cuda_runtime.h>
#include <math.h>

#define N_ITER 10
#define UPD_CHUNK 48

static __device__ float d_p[5];                     // separable 1D psf
static __device__ float d_q[9];                     // q = p (*) p  (9-tap)
static __device__ float d_E[96 * 192 * 192];        // conv_xy(residual) planes
static __device__ float d_A[192 * 192 * 192];       // ping
static __device__ float d_B[192 * 192 * 192];       // spec: S~ ; gen: pong

// ---------------------------------------------------------------------------
// packed f32x2 helpers (Blackwell)
// ---------------------------------------------------------------------------
__device__ __forceinline__ unsigned long long pk2(float lo, float hi) {
    unsigned long long r;
    asm("mov.b64 %0, {%1, %2};" : "=l"(r) : "f"(lo), "f"(hi));
    return r;
}
__device__ __forceinline__ void upk2(unsigned long long v, float& lo, float& hi) {
    asm("mov.b64 {%0, %1}, %2;" : "=f"(lo), "=f"(hi) : "l"(v));
}
__device__ __forceinline__ unsigned long long fma2_(unsigned long long a,
                                                    unsigned long long b,
                                                    unsigned long long c) {
    unsigned long long d;
    asm("fma.rn.f32x2 %0, %1, %2, %3;" : "=l"(d) : "l"(a), "l"(b), "l"(c));
    return d;
}
__device__ __forceinline__ unsigned long long mul2_(unsigned long long a,
                                                    unsigned long long b) {
    unsigned long long d;
    asm("mul.rn.f32x2 %0, %1, %2;" : "=l"(d) : "l"(a), "l"(b));
    return d;
}

// ---------------------------------------------------------------------------
__global__ void init_p_kernel(const float* __restrict__ psf) {
    if (threadIdx.x == 0) {
        float p[5];
        for (int i = 0; i < 5; ++i) {
            float s = 0.f;
            for (int j = 0; j < 25; ++j) s += psf[i * 25 + j];
            p[i] = s;
            d_p[i] = s;
        }
        for (int i = 0; i < 9; ++i) {
            float s = 0.f;
            for (int a = 0; a < 5; ++a) {
                int b = i - a;
                if (b >= 0 && b < 5) s += p[a] * p[b];
            }
            d_q[i] = s;
        }
    }
}

// ===========================================================================
// S~ = conv_p2d(slices), computed ONCE per launch. spec dims (H,W mult of 32).
// ===========================================================================
template <int H, int W>
__global__ __launch_bounds__(256) void stilde_t(
    const float* __restrict__ slices, float* __restrict__ St) {
    constexpr int HW = H * W;
    __shared__ float sIn[36][38];
    __shared__ float sMid[36][33];

    const int i = blockIdx.z;
    const int x0 = blockIdx.x * 32, y0 = blockIdx.y * 32;
    const int tx = threadIdx.x, ty = threadIdx.y;
    const float p0 = d_p[0], p1 = d_p[1], p2 = d_p[2], p3 = d_p[3], p4 = d_p[4];
    const float* sl = slices + i * HW;

    // load 36x36 halo (zero outside image)
    #pragma unroll
    for (int k = 0; k < 5; ++k) {
        const int r = (k < 4) ? (ty + 8 * k) : (32 + ty);
        if (k == 4 && ty >= 4) break;
        const int gy = y0 - 2 + r;
        const bool okY = (unsigned)gy < (unsigned)H;
        #pragma unroll
        for (int b = 0; b < 2; ++b) {
            if (b == 1 && tx >= 4) break;
            const int c = b * 32 + tx;
            const int gx = x0 - 2 + c;
            sIn[r][c] = (okY && (unsigned)gx < (unsigned)W) ? sl[gy * W + gx] : 0.f;
        }
    }
    __syncthreads();

    // x-conv (36 rows x 32 cols)
    #pragma unroll
    for (int k = 0; k < 5; ++k) {
        const int r = (k < 4) ? (ty + 8 * k) : (32 + ty);
        if (k == 4 && ty >= 4) break;
        sMid[r][tx] = p0 * sIn[r][tx]     + p1 * sIn[r][tx + 1] + p2 * sIn[r][tx + 2]
                    + p3 * sIn[r][tx + 3] + p4 * sIn[r][tx + 4];
    }
    __syncthreads();

    // y-conv, store (32 x 32)
    float* Si = St + i * HW + y0 * W + x0;
    #pragma unroll
    for (int k = 0; k < 4; ++k) {
        const int r = ty + 8 * k;
        Si[r * W + tx] = p0 * sMid[r][tx]     + p1 * sMid[r + 1][tx]
                       + p2 * sMid[r + 2][tx] + p3 * sMid[r + 3][tx]
                       + p4 * sMid[r + 4][tx];
    }
}

// ===========================================================================
// fused_E v3 (spec): E = conv_p2d(conv_p2d(conv_z x) zeroed) - S~.
// Interior tiles (outputs >=2 from image edge): single 9-tap q conv (3 stages).
// Boundary tiles: validated 5-stage path (F zeroed outside), minus slice load.
// 2 slices per block (shared 7-plane z window when stride==2).
// ===========================================================================
template <int D, int H, int W, int NS>
__global__ __launch_bounds__(256, 5) void fused_E3_t(
    const float* __restrict__ x, const float* __restrict__ St,
    float* __restrict__ E, const int* __restrict__ stridep) {
    constexpr int HW = H * W;
    __shared__ float bufZ[2][40][42];   // stage1 out; boundary: sF overlay (36x37)
    __shared__ float bufA[2][40][37];   // stage2 out; boundary: sB overlay (36x33)

    const int pr = blockIdx.z;
    const int stride = *stridep;
    const int iA = 2 * pr;
    const int ziA = iA * stride;
    const int x0 = blockIdx.x * 32, y0 = blockIdx.y * 32;
    const int tx = threadIdx.x, ty = threadIdx.y;

    const float p0 = d_p[0], p1 = d_p[1], p2 = d_p[2], p3 = d_p[3], p4 = d_p[4];

    const bool intXY = (x0 >= 4) && (x0 + 36 <= W) && (y0 >= 4) && (y0 + 36 <= H);
    // q-form valid when all outputs are >= 2 from the image edge
    const bool interior = (x0 >= 2) && (x0 + 34 <= W) && (y0 >= 2) && (y0 + 34 <= H);

    // ---- stage 1: z-combine both slices into bufZ (40x40, halo 4) ----
    if (stride == 2) {
        const int q0 = ziA - 2;                  // planes q0 .. q0+6
        const bool intZ = (q0 >= 0) && (ziA + 4 < D);
        if (intZ && intXY) {
            const float* base = x + q0 * HW + (y0 - 4) * W + (x0 - 4);
            #pragma unroll
            for (int k = 0; k < 5; ++k) {
                const int r = ty + 8 * k;
                const float* rowp = base + r * W;
                #pragma unroll
                for (int b = 0; b < 2; ++b) {
                    if (b == 1 && tx >= 8) break;
                    const int c = b * 32 + tx;
                    const float* col = rowp + c;
                    const float v0 = col[0],      v1 = col[HW],     v2 = col[2 * HW];
                    const float v3 = col[3 * HW], v4 = col[4 * HW], v5 = col[5 * HW];
                    const float v6 = col[6 * HW];
                    bufZ[0][r][c] = p0 * v0 + p1 * v1 + p2 * v2 + p3 * v3 + p4 * v4;
                    bufZ[1][r][c] = p0 * v2 + p1 * v3 + p2 * v4 + p3 * v5 + p4 * v6;
                }
            }
        } else {
            bool qok[7];
            #pragma unroll
            for (int j = 0; j < 7; ++j) qok[j] = (unsigned)(q0 + j) < (unsigned)D;
            #pragma unroll
            for (int k = 0; k < 5; ++k) {
                const int r = ty + 8 * k;
                const int gy = y0 - 4 + r;
                const bool okY = (unsigned)gy < (unsigned)H;
                #pragma unroll
                for (int b = 0; b < 2; ++b) {
                    if (b == 1 && tx >= 8) break;
                    const int c = b * 32 + tx;
                    const int gx = x0 - 4 + c;
                    const bool okXY = okY && (unsigned)gx < (unsigned)W;
                    const float* col = x + gy * W + gx;
                    float v[7];
                    #pragma unroll
                    for (int j = 0; j < 7; ++j)
                        v[j] = (okXY && qok[j]) ? col[(q0 + j) * HW] : 0.f;
                    bufZ[0][r][c] = p0 * v[0] + p1 * v[1] + p2 * v[2] + p3 * v[3] + p4 * v[4];
                    bufZ[1][r][c] = p0 * v[2] + p1 * v[3] + p2 * v[4] + p3 * v[5] + p4 * v[6];
                }
            }
        }
    } else {
        #pragma unroll
        for (int s = 0; s < 2; ++s) {
            const int zi = (iA + s) * stride;
            const int z0 = zi - 2;
            bool zok[5];
            #pragma unroll
            for (int j = 0; j < 5; ++j) zok[j] = (unsigned)(z0 + j) < (unsigned)D;
            #pragma unroll
            for (int k = 0; k < 5; ++k) {
                const int r = ty + 8 * k;
                const int gy = y0 - 4 + r;
                const bool okY = (unsigned)gy < (unsigned)H;
                #pragma unroll
                for (int b = 0; b < 2; ++b) {
                    if (b == 1 && tx >= 8) break;
                    const int c = b * 32 + tx;
                    const int gx = x0 - 4 + c;
                    const bool okXY = okY && (unsigned)gx < (unsigned)W;
                    const float* col = x + gy * W + gx;
                    float acc = 0.f;
                    if (okXY) {
                        if (zok[0]) acc = fmaf(p0, col[(z0 + 0) * HW], acc);
                        if (zok[1]) acc = fmaf(p1, col[(z0 + 1) * HW], acc);
                        if (zok[2]) acc = fmaf(p2, col[(z0 + 2) * HW], acc);
                        if (zok[3]) acc = fmaf(p3, col[(z0 + 3) * HW], acc);
                        if (zok[4]) acc = fmaf(p4, col[(z0 + 4) * HW], acc);
                    }
                    bufZ[s][r][c] = acc;
                }
            }
        }
    }
    __syncthreads();

    if (interior) {
        // ---- FAST PATH: single 9-tap conv q2d ----
        const float q0_ = d_q[0], q1_ = d_q[1], q2_ = d_q[2], q3_ = d_q[3];
        const float q4_ = d_q[4], q5_ = d_q[5], q6_ = d_q[6], q7_ = d_q[7];
        const float q8_ = d_q[8];

        // S2: 9-tap x-conv (40 rows x 32 cols)
        #pragma unroll
        for (int s = 0; s < 2; ++s) {
            #pragma unroll
            for (int k = 0; k < 5; ++k) {
                const int r = ty + 8 * k;
                const float* zr = &bufZ[s][r][tx];
                bufA[s][r][tx] = q0_ * zr[0] + q1_ * zr[1] + q2_ * zr[2]
                               + q3_ * zr[3] + q4_ * zr[4] + q5_ * zr[5]
                               + q6_ * zr[6] + q7_ * zr[7] + q8_ * zr[8];
            }
        }
        __syncthreads();

        // S3: 9-tap y-conv, subtract S~, store (32 x 32)
        #pragma unroll
        for (int s = 0; s < 2; ++s) {
            float* Ei = E + (iA + s) * HW + y0 * W + x0;
            const float* Si = St + (iA + s) * HW + y0 * W + x0;
            #pragma unroll
            for (int k = 0; k < 4; ++k) {
                const int r = ty + 8 * k;
                float v = q0_ * bufA[s][r][tx]     + q1_ * bufA[s][r + 1][tx]
                        + q2_ * bufA[s][r + 2][tx] + q3_ * bufA[s][r + 3][tx]
                        + q4_ * bufA[s][r + 4][tx] + q5_ * bufA[s][r + 5][tx]
                        + q6_ * bufA[s][r + 6][tx] + q7_ * bufA[s][r + 7][tx]
                        + q8_ * bufA[s][r + 8][tx];
                Ei[r * W + tx] = v - Si[r * W + tx];
            }
        }
        return;
    }

    // ---- BOUNDARY PATH: 5-stage (F zeroed outside image), subtract S~ ----
    // stage 2: x-conv into bufA (40 x 36)
    #pragma unroll
    for (int s = 0; s < 2; ++s) {
        #pragma unroll
        for (int k = 0; k < 5; ++k) {
            const int r = ty + 8 * k;
            bufA[s][r][tx] = p0 * bufZ[s][r][tx]     + p1 * bufZ[s][r][tx + 1]
                           + p2 * bufZ[s][r][tx + 2] + p3 * bufZ[s][r][tx + 3]
                           + p4 * bufZ[s][r][tx + 4];
            if (tx < 4) {
                const int c = 32 + tx;
                bufA[s][r][c] = p0 * bufZ[s][r][c]     + p1 * bufZ[s][r][c + 1]
                              + p2 * bufZ[s][r][c + 2] + p3 * bufZ[s][r][c + 3]
                              + p4 * bufZ[s][r][c + 4];
            }
        }
    }
    __syncthreads();

    // stage 3: y-conv into sF (36 x 36, overlays bufZ; 0 outside image)
    {
        float (*sF0)[37] = (float (*)[37]) &bufZ[0][0][0];
        float (*sF1)[37] = (float (*)[37]) &bufZ[1][0][0];
        #pragma unroll
        for (int s = 0; s < 2; ++s) {
            float (*sF)[37] = s ? sF1 : sF0;
            #pragma unroll
            for (int k = 0; k < 5; ++k) {
                const int r = (k < 4) ? (ty + 8 * k) : (32 + ty);
                if (k == 4 && ty >= 4) break;
                const int gy = y0 - 2 + r;
                const bool okY = (unsigned)gy < (unsigned)H;
                #pragma unroll
                for (int b = 0; b < 2; ++b) {
                    if (b == 1 && tx >= 4) break;
                    const int c = b * 32 + tx;
                    const int gx = x0 - 2 + c;
                    float v = 0.f;
                    if (okY && (unsigned)gx < (unsigned)W) {
                        v = p0 * bufA[s][r][c]     + p1 * bufA[s][r + 1][c]
                          + p2 * bufA[s][r + 2][c] + p3 * bufA[s][r + 3][c]
                          + p4 * bufA[s][r + 4][c];
                    }
                    sF[r][c] = v;
                }
            }
        }
    }
    __syncthreads();

    // stage 4: x-conv into sB (36 x 32, overlays bufA)
    {
        float (*sF0)[37] = (float (*)[37]) &bufZ[0][0][0];
        float (*sF1)[37] = (float (*)[37]) &bufZ[1][0][0];
        float (*sB0)[33] = (float (*)[33]) &bufA[0][0][0];
        float (*sB1)[33] = (float (*)[33]) &bufA[1][0][0];
        #pragma unroll
        for (int s = 0; s < 2; ++s) {
            float (*sF)[37] = s ? sF1 : sF0;
            float (*sB)[33] = s ? sB1 : sB0;
            #pragma unroll
            for (int k = 0; k < 5; ++k) {
                const int r = (k < 4) ? (ty + 8 * k) : (32 + ty);
                if (k == 4 && ty >= 4) break;
                sB[r][tx] = p0 * sF[r][tx]     + p1 * sF[r][tx + 1] + p2 * sF[r][tx + 2]
                          + p3 * sF[r][tx + 3] + p4 * sF[r][tx + 4];
            }
        }
    }
    __syncthreads();

    // stage 5: y-conv, subtract S~, store (32 x 32 each)
    {
        float (*sB0)[33] = (float (*)[33]) &bufA[0][0][0];
        float (*sB1)[33] = (float (*)[33]) &bufA[1][0][0];
        #pragma unroll
        for (int s = 0; s < 2; ++s) {
            float (*sB)[33] = s ? sB1 : sB0;
            float* Ei = E + (iA + s) * HW + y0 * W + x0;
            const float* Si = St + (iA + s) * HW + y0 * W + x0;
            #pragma unroll
            for (int k = 0; k < 4; ++k) {
                const int r = ty + 8 * k;
                float v = p0 * sB[r][tx]     + p1 * sB[r + 1][tx]
                        + p2 * sB[r + 2][tx] + p3 * sB[r + 3][tx]
                        + p4 * sB[r + 4][tx];
                Ei[r * W + tx] = v - Si[r * W + tx];
            }
        }
    }
}

// ---------------------------------------------------------------------------
// update: 2 z per barrier, packed f32x2 regularizer for the voxel pair.
// (unchanged from the validated R7/R11 kernel; UPD_CHUNK now 48)
template <int D, int H, int W, int NS>
__global__ __launch_bounds__(256, 4) void update2_t(
    const float* __restrict__ xin, const float* __restrict__ E,
    float* __restrict__ xout, const int* __restrict__ stridep, int do_relu) {
    constexpr int HW = H * W;
    __shared__ float s[4][10][36];

    const int x0 = blockIdx.x * 32, y0 = blockIdx.y * 8;
    const int zb = blockIdx.z * UPD_CHUNK;        // even
    const int tx = threadIdx.x, ty = threadIdx.y;
    const int tid = ty * 32 + tx;
    const int y = y0 + ty, x = x0 + tx;
    const int stride = *stridep;

    const float p0 = d_p[0], p1 = d_p[1], p2 = d_p[2], p3 = d_p[3], p4 = d_p[4];

    const float w1 = (float)(1.0 / (1.0 * 0.1 * 0.1));
    const float w2 = (float)(1.0 / (2.0 * 0.1 * 0.1));
    const float w3 = (float)(1.0 / (3.0 * 0.1 * 0.1));

    const int ly0 = tid / 34, lx0 = tid % 34;
    const int gy0 = y0 - 1 + ly0, gx0 = x0 - 1 + lx0;
    const bool ok0 = (unsigned)gy0 < (unsigned)H && (unsigned)gx0 < (unsigned)W;
    const int off0 = ok0 ? (gy0 * W + gx0) : 0;

    const int i1 = tid + 256;
    const bool has1 = (i1 < 340);
    const int ly1 = has1 ? i1 / 34 : 0, lx1 = has1 ? i1 % 34 : 0;
    const int gy1 = y0 - 1 + ly1, gx1 = x0 - 1 + lx1;
    const bool ok1 = has1 && (unsigned)gy1 < (unsigned)H && (unsigned)gx1 < (unsigned)W;
    const int off1 = ok1 ? (gy1 * W + gx1) : 0;

    auto loadPlane = [&](int z, int sl) {
        const bool zok = (unsigned)z < (unsigned)D;
        const int zo = (zok ? z : 0) * HW;
        s[sl][ly0][lx0] = (zok && ok0) ? xin[zo + off0] : 0.f;
        if (has1) s[sl][ly1][lx1] = (zok && ok1) ? xin[zo + off1] : 0.f;
    };

    loadPlane(zb - 1, (zb - 1) & 3);
    loadPlane(zb, zb & 3);
    __syncthreads();

    float A[9], B[9];
    {
        const int sm = (zb - 1) & 3, s0 = zb & 3;
        #pragma unroll
        for (int dy = 0; dy < 3; ++dy)
            #pragma unroll
            for (int dx = 0; dx < 3; ++dx) {
                A[dy * 3 + dx] = s[sm][ty + dy][tx + dx];
                B[dy * 3 + dx] = s[s0][ty + dy][tx + dx];
            }
    }

    const bool interior_xy = (y > 0 && y < H - 1 && x > 0 && x < W - 1);
    const int eo = y * W + x;
    const float* Ecol = E + eo;
    float* outcol = xout + eo;
    const float ALPHA = 0.5f;
    const float BETA = (float)(0.02 * 0.1 * 0.1);

    auto regTerm = [&](const float* Av, const float* Bv, const float* Cv) -> float {
        float greg = 0.f;
        const float v0 = Bv[4];
        #pragma unroll
        for (int j = 0; j < 9; ++j) {
            const int dy = j / 3 - 1, dx = j % 3 - 1;
            const int d2a = dy * dy + dx * dx + 1;
            const float wa = (d2a == 1) ? w1 : ((d2a == 2) ? w2 : w3);
            { float dv = v0 - Av[j]; float t = dv * wa; greg += t * rsqrtf(fmaf(dv, t, 1.0f)); }
            { float dv = v0 - Cv[j]; float t = dv * wa; greg += t * rsqrtf(fmaf(dv, t, 1.0f)); }
            if (j != 4) {
                const int d2b = dy * dy + dx * dx;
                const float wb = (d2b == 1) ? w1 : ((d2b == 2) ? w2 : w3);
                float dv = v0 - Bv[j]; float t = dv * wb;
                greg += t * rsqrtf(fmaf(dv, t, 1.0f));
            }
        }
        return greg;
    };

    const int zend = (zb + UPD_CHUNK < D) ? (zb + UPD_CHUNK) : D;

    if (stride == 2) {
        int h = zb >> 1;
        float eA = (h >= 1) ? Ecol[(h - 1) * HW] : 0.f;
        float eB = (h < NS) ? Ecol[h * HW] : 0.f;
        float eC = (h + 1 < NS) ? Ecol[(h + 1) * HW] : 0.f;

        for (int z = zb; z < zend; z += 2, ++h) {
            const int s1 = (z + 1) & 3, s2 = (z + 2) & 3;
            loadPlane(z + 1, s1);
            loadPlane(z + 2, s2);
            __syncthreads();

            float C1[9], C2[9];
            #pragma unroll
            for (int dy = 0; dy < 3; ++dy)
                #pragma unroll
                for (int dx = 0; dx < 3; ++dx) {
                    C1[dy * 3 + dx] = s[s1][ty + dy][tx + dx];
                    C2[dy * 3 + dx] = s[s2][ty + dy][tx + dx];
                }

            float ge = 0.f, go = 0.f;
            if (interior_xy) {
                const unsigned long long v0p  = pk2(B[4], C1[4]);
                const unsigned long long one2 = pk2(1.0f, 1.0f);
                const unsigned long long m12  = pk2(-1.0f, -1.0f);
                unsigned long long acc = pk2(0.0f, 0.0f);

                #pragma unroll
                for (int j = 0; j < 9; ++j) {
                    const int dy = j / 3 - 1, dx = j % 3 - 1;
                    const int d2 = dy * dy + dx * dx;
                    const float wa = (d2 == 0) ? w1 : ((d2 == 1) ? w2 : w3);
                    {
                        const unsigned long long np = pk2(A[j], B[j]);
                        const unsigned long long dv = fma2_(np, m12, v0p);
                        const unsigned long long wp = pk2(wa, wa);
                        const unsigned long long t  = mul2_(dv, wp);
                        const unsigned long long ar = fma2_(dv, t, one2);
                        float a0, a1; upk2(ar, a0, a1);
                        acc = fma2_(t, pk2(rsqrtf(a0), rsqrtf(a1)), acc);
                    }
                    {
                        const unsigned long long np = pk2(C1[j], C2[j]);
                        const unsigned long long dv = fma2_(np, m12, v0p);
                        const unsigned long long wp = pk2(wa, wa);
                        const unsigned long long t  = mul2_(dv, wp);
                        const unsigned long long ar = fma2_(dv, t, one2);
                        float a0, a1; upk2(ar, a0, a1);
                        acc = fma2_(t, pk2(rsqrtf(a0), rsqrtf(a1)), acc);
                    }
                    if (j != 4) {
                        const float wb = (d2 == 1) ? w1 : w2;
                        const unsigned long long np = pk2(B[j], C1[j]);
                        const unsigned long long dv = fma2_(np, m12, v0p);
                        const unsigned long long wp = pk2(wb, wb);
                        const unsigned long long t  = mul2_(dv, wp);
                        const unsigned long long ar = fma2_(dv, t, one2);
                        float a0, a1; upk2(ar, a0, a1);
                        acc = fma2_(t, pk2(rsqrtf(a0), rsqrtf(a1)), acc);
                    }
                }
                upk2(acc, ge, go);
                if (z == 0) ge = 0.f;
                if (z + 1 == D - 1) go = 0.f;
            }

            {
                float gd = fmaf(p0, eA, fmaf(p2, eB, p4 * eC));
                float xn = B[4] - ALPHA * (gd + BETA * ge);
                if (do_relu) xn = fmaxf(xn, 0.f);
                outcol[z * HW] = xn;
            }
            {
                float gd = fmaf(p1, eB, p3 * eC);
                float xn = C1[4] - ALPHA * (gd + BETA * go);
                if (do_relu) xn = fmaxf(xn, 0.f);
                outcol[(z + 1) * HW] = xn;
            }

            #pragma unroll
            for (int j = 0; j < 9; ++j) { A[j] = C1[j]; B[j] = C2[j]; }
            eA = eB; eB = eC;
            eC = (h + 2 < NS) ? Ecol[(h + 2) * HW] : 0.f;
        }
    } else {
        const float pz[5] = {p0, p1, p2, p3, p4};
        for (int z = zb; z < zend; ++z) {
            const int sl = (z + 1) & 3;
            loadPlane(z + 1, sl);
            __syncthreads();
            float C[9];
            #pragma unroll
            for (int dy = 0; dy < 3; ++dy)
                #pragma unroll
                for (int dx = 0; dx < 3; ++dx)
                    C[dy * 3 + dx] = s[sl][ty + dy][tx + dx];

            float gd = 0.f;
            #pragma unroll
            for (int dz = 0; dz < 5; ++dz) {
                int zz = z + dz - 2;
                if ((unsigned)zz < (unsigned)D && (zz % stride) == 0) {
                    int pi = zz / stride;
                    if (pi < NS) gd = fmaf(pz[dz], Ecol[pi * HW], gd);
                }
            }
            float greg = 0.f;
            if (interior_xy && z > 0 && z < D - 1) greg = regTerm(A, B, C);
            float xn = B[4] - ALPHA * (gd + BETA * greg);
            if (do_relu) xn = fmaxf(xn, 0.f);
            outcol[z * HW] = xn;
            #pragma unroll
            for (int j = 0; j < 9; ++j) { A[j] = B[j]; B[j] = C[j]; }
        }
    }
}

// ===========================================================================
// Generic fallback kernels (runtime dims) — validated in R4/R5.
// ===========================================================================

__global__ __launch_bounds__(256) void fused_E_gen(
    const float* __restrict__ x, const float* __restrict__ slices,
    float* __restrict__ E, const int* __restrict__ stridep,
    int D, int H, int W, int n_slices) {
    __shared__ float sZ[40][44];
    __shared__ float sA[40][36];
    __shared__ float sF[36][36];
    __shared__ float sB[36][33];

    const int i = blockIdx.z;
    const int zi = i * (*stridep);
    const int x0 = blockIdx.x * 32, y0 = blockIdx.y * 32;
    const int tx = threadIdx.x, ty = threadIdx.y;
    const size_t HW = (size_t)H * W;

    const float p0 = d_p[0], p1 = d_p[1], p2 = d_p[2], p3 = d_p[3], p4 = d_p[4];

    {
        const int z0 = zi - 2;
        const bool zok0 = (z0 >= 0), zok1 = (z0 + 1 >= 0);
        const bool zok2 = (z0 + 2 >= 0) && (z0 + 2 < D);
        const bool zok3 = (z0 + 3 < D), zok4 = (z0 + 4 < D);
        #pragma unroll
        for (int k = 0; k < 5; ++k) {
            const int r = ty + 8 * k;
            const int gy = y0 - 4 + r;
            const bool okY = (unsigned)gy < (unsigned)H;
            #pragma unroll
            for (int b = 0; b < 2; ++b) {
                const int c = b * 32 + tx;
                if (b == 1 && tx >= 8) break;
                const int gx = x0 - 4 + c;
                float acc = 0.f;
                if (okY && (unsigned)gx < (unsigned)W) {
                    const float* col = x + (size_t)gy * W + gx + (size_t)z0 * HW;
                    if (zok0) acc = fmaf(p0, col[0], acc);
                    if (zok1) acc = fmaf(p1, col[HW], acc);
                    if (zok2) acc = fmaf(p2, col[2 * HW], acc);
                    if (zok3) acc = fmaf(p3, col[3 * HW], acc);
                    if (zok4) acc = fmaf(p4, col[4 * HW], acc);
                }
                sZ[r][c] = acc;
            }
        }
    }
    __syncthreads();

    #pragma unroll
    for (int k = 0; k < 5; ++k) {
        const int r = ty + 8 * k;
        sA[r][tx] = p0 * sZ[r][tx]     + p1 * sZ[r][tx + 1] + p2 * sZ[r][tx + 2]
                  + p3 * sZ[r][tx + 3] + p4 * sZ[r][tx + 4];
        if (tx < 4) {
            const int c = 32 + tx;
            sA[r][c] = p0 * sZ[r][c]     + p1 * sZ[r][c + 1] + p2 * sZ[r][c + 2]
                     + p3 * sZ[r][c + 3] + p4 * sZ[r][c + 4];
        }
    }
    __syncthreads();

    {
        const float* sl = slices + (size_t)i * HW;
        #pragma unroll
        for (int k = 0; k < 5; ++k) {
            const int r = (k < 4) ? (ty + 8 * k) : (32 + ty);
            if (k == 4 && ty >= 4) break;
            const int gy = y0 - 2 + r;
            const bool okY = (unsigned)gy < (unsigned)H;
            #pragma unroll
            for (int b = 0; b < 2; ++b) {
                const int c = b * 32 + tx;
                if (b == 1 && tx >= 4) break;
                const int gx = x0 - 2 + c;
                float v = 0.f;
                if (okY && (unsigned)gx < (unsigned)W) {
                    v = p0 * sA[r][c]     + p1 * sA[r + 1][c] + p2 * sA[r + 2][c]
                      + p3 * sA[r + 3][c] + p4 * sA[r + 4][c]
                      - sl[(size_t)gy * W + gx];
                }
                sF[r][c] = v;
            }
        }
    }
    __syncthreads();

    #pragma unroll
    for (int k = 0; k < 5; ++k) {
        const int r = (k < 4) ? (ty + 8 * k) : (32 + ty);
        if (k == 4 && ty >= 4) break;
        sB[r][tx] = p0 * sF[r][tx]     + p1 * sF[r][tx + 1] + p2 * sF[r][tx + 2]
                  + p3 * sF[r][tx + 3] + p4 * sF[r][tx + 4];
    }
    __syncthreads();

    {
        float* Ei = E + (size_t)i * HW;
        #pragma unroll
        for (int k = 0; k < 4; ++k) {
            const int r = ty + 8 * k;
            const int gy = y0 + r, gx = x0 + tx;
            if (gy < H && gx < W) {
                Ei[(size_t)gy * W + gx] =
                      p0 * sB[r][tx]     + p1 * sB[r + 1][tx] + p2 * sB[r + 2][tx]
                    + p3 * sB[r + 3][tx] + p4 * sB[r + 4][tx];
            }
        }
    }
}

__global__ __launch_bounds__(256, 4) void update_gen(
    const float* __restrict__ xin, const float* __restrict__ E,
    float* __restrict__ xout, const int* __restrict__ stridep,
    int n_slices, int D, int H, int W, int do_relu) {
    __shared__ float s[3][10][36];

    const int x0 = blockIdx.x * 32, y0 = blockIdx.y * 8;
    const int zb = blockIdx.z * UPD_CHUNK;
    const int tx = threadIdx.x, ty = threadIdx.y;
    const int tid = ty * 32 + tx;
    const size_t HW = (size_t)H * W;
    const int y = y0 + ty, x = x0 + tx;
    const int stride = *stridep;

    const float p0 = d_p[0], p1 = d_p[1], p2 = d_p[2], p3 = d_p[3], p4 = d_p[4];
    const float pz[5] = {p0, p1, p2, p3, p4};
    const float w1 = (float)(1.0 / (1.0 * 0.1 * 0.1));
    const float w2 = (float)(1.0 / (2.0 * 0.1 * 0.1));
    const float w3 = (float)(1.0 / (3.0 * 0.1 * 0.1));

    const int ly0 = tid / 34, lx0 = tid % 34;
    const int gy0 = y0 - 1 + ly0, gx0 = x0 - 1 + lx0;
    const bool ok0 = (unsigned)gy0 < (unsigned)H && (unsigned)gx0 < (unsigned)W;
    const size_t off0 = ok0 ? ((size_t)gy0 * W + gx0) : 0;
    const int i1 = tid + 256;
    const bool has1 = (i1 < 340);
    const int ly1 = has1 ? i1 / 34 : 0, lx1 = has1 ? i1 % 34 : 0;
    const int gy1 = y0 - 1 + ly1, gx1 = x0 - 1 + lx1;
    const bool ok1 = has1 && (unsigned)gy1 < (unsigned)H && (unsigned)gx1 < (unsigned)W;
    const size_t off1 = ok1 ? ((size_t)gy1 * W + gx1) : 0;

    auto loadPlane = [&](int z, int sl) {
        const bool zok = (unsigned)z < (unsigned)D;
        const size_t zo = (size_t)(zok ? z : 0) * HW;
        s[sl][ly0][lx0] = (zok && ok0) ? xin[zo + off0] : 0.f;
        if (has1) s[sl][ly1][lx1] = (zok && ok1) ? xin[zo + off1] : 0.f;
    };

    const int sl_m1 = ((zb - 1) % 3 + 3) % 3;
    const int sl_0  = zb % 3;
    loadPlane(zb - 1, sl_m1);
    loadPlane(zb, sl_0);
    __syncthreads();

    float A[9], B[9];
    #pragma unroll
    for (int dy = 0; dy < 3; ++dy)
        #pragma unroll
        for (int dx = 0; dx < 3; ++dx) {
            A[dy * 3 + dx] = s[sl_m1][ty + dy][tx + dx];
            B[dy * 3 + dx] = s[sl_0][ty + dy][tx + dx];
        }

    const bool interior_xy = (y > 0 && y < H - 1 && x > 0 && x < W - 1);
    const size_t eo = (size_t)y * W + x;
    const float* Ecol = E + eo;
    float* outcol = xout + eo;
    const float ALPHA = 0.5f;
    const float BETA = (float)(0.02 * 0.1 * 0.1);

    int zend = zb + UPD_CHUNK;
    if (zend > D) zend = D;

    for (int z = zb; z < zend; ++z) {
        const int sl = (z + 1) % 3;
        loadPlane(z + 1, sl);
        __syncthreads();

        float C[9];
        #pragma unroll
        for (int dy = 0; dy < 3; ++dy)
            #pragma unroll
            for (int dx = 0; dx < 3; ++dx)
                C[dy * 3 + dx] = s[sl][ty + dy][tx + dx];

        const float v0 = B[4];
        float gd = 0.f;
        #pragma unroll
        for (int dz = 0; dz < 5; ++dz) {
            int zz = z + dz - 2;
            if ((unsigned)zz < (unsigned)D && (zz % stride) == 0) {
                int pi = zz / stride;
                if (pi < n_slices) gd = fmaf(pz[dz], Ecol[(size_t)pi * HW], gd);
            }
        }

        float greg = 0.f;
        if (interior_xy && z > 0 && z < D - 1) {
            #pragma unroll
            for (int j = 0; j < 9; ++j) {
                const int dy = j / 3 - 1, dx = j % 3 - 1;
                const int d2a = dy * dy + dx * dx + 1;
                const float wa = (d2a == 1) ? w1 : ((d2a == 2) ? w2 : w3);
                { float dv = v0 - A[j]; float t = dv * wa; greg += t * rsqrtf(fmaf(dv, t, 1.0f)); }
                { float dv = v0 - C[j]; float t = dv * wa; greg += t * rsqrtf(fmaf(dv, t, 1.0f)); }
                if (j != 4) {
                    const int d2b = dy * dy + dx * dx;
                    const float wb = (d2b == 1) ? w1 : ((d2b == 2) ? w2 : w3);
                    float dv = v0 - B[j]; float t = dv * wb;
                    greg += t * rsqrtf(fmaf(dv, t, 1.0f));
                }
            }
        }

        float xn = v0 - ALPHA * (gd + BETA * greg);
        if (do_relu) xn = fmaxf(xn, 0.f);
        outcol[(size_t)z * HW] = xn;

        #pragma unroll
        for (int j = 0; j < 9; ++j) { A[j] = B[j]; B[j] = C[j]; }
    }
}

// ---------------------------------------------------------------------------
extern "C" void kernel_launch(void* const* d_in, const int* in_sizes, int n_in,
                              void* d_out, int out_size) {
    const float* slices = (const float*)d_in[1];
    const float* volume = (const float*)d_in[2];
    const float* psf    = (const float*)d_in[3];
    const int* stridep  = (const int*)d_in[4];

    int D = (int)lround(cbrt((double)out_size));   // 192
    int H = D, W = D;
    int n_slices = in_sizes[1] / (H * W);

    float *pE, *pA, *pB;
    cudaGetSymbolAddress((void**)&pE, d_E);
    cudaGetSymbolAddress((void**)&pA, d_A);
    cudaGetSymbolAddress((void**)&pB, d_B);

    init_p_kernel<<<1, 32>>>(psf);

    const bool spec = (D == 192 && H == 192 && W == 192 && n_slices == 96);

    dim3 blkE(32, 8, 1);
    dim3 grid_E2((W + 31) / 32, (H + 31) / 32, n_slices / 2);
    dim3 grid_E((W + 31) / 32, (H + 31) / 32, n_slices);
    dim3 blkU(32, 8, 1);
    dim3 grid_up((W + 31) / 32, (H + 7) / 8, (D + UPD_CHUNK - 1) / UPD_CHUNK);

    if (spec) {
        // one-time: S~ = conv_p2d(slices) into pB
        stilde_t<192, 192><<<dim3(6, 6, 96), blkE>>>(slices, pB);
        for (int it = 0; it < N_ITER; ++it) {
            const float* xin = (it == 0) ? volume
                                         : ((it & 1) ? pA : (const float*)d_out);
            float* xout = (it & 1) ? (float*)d_out : pA;
            int do_relu = (it == N_ITER - 1) ? 1 : 0;
            fused_E3_t<192, 192, 192, 96><<<grid_E2, blkE>>>(xin, pB, pE, stridep);
            update2_t<192, 192, 192, 96><<<grid_up, blkU>>>(xin, pE, xout, stridep, do_relu);
        }
    } else {
        for (int it = 0; it < N_ITER; ++it) {
            const float* xin = (it == 0) ? volume : ((it & 1) ? pA : pB);
            float* xout = (it == N_ITER - 1) ? (float*)d_out
                                             : ((it & 1) ? pB : pA);
            int do_relu = (it == N_ITER - 1) ? 1 : 0;
            fused_E_gen<<<grid_E, blkE>>>(xin, slices, pE, stridep, D, H, W, n_slices);
            update_gen<<<grid_up, blkU>>>(xin, pE, xout, stridep, n_slices, D, H, W, do_relu);
        }
    }
}

// round 13
// speedup vs baseline: 1.5104x; 1.0076x over previous
#include <cuda_runtime.h>
#include <math.h>

#define N_ITER 10
#define UPD_CHUNK 24

static __device__ float d_p[5];                     // separable 1D psf
static __device__ float d_q[9];                     // q = p (*) p  (9-tap)
static __device__ float d_E[96 * 192 * 192];        // conv_xy(residual) planes
static __device__ float d_A[192 * 192 * 192];       // ping
static __device__ float d_B[192 * 192 * 192];       // spec: S~ ; gen: pong

// ---------------------------------------------------------------------------
// packed f32x2 helpers (Blackwell)
// ---------------------------------------------------------------------------
__device__ __forceinline__ unsigned long long pk2(float lo, float hi) {
    unsigned long long r;
    asm("mov.b64 %0, {%1, %2};" : "=l"(r) : "f"(lo), "f"(hi));
    return r;
}
__device__ __forceinline__ void upk2(unsigned long long v, float& lo, float& hi) {
    asm("mov.b64 {%0, %1}, %2;" : "=f"(lo), "=f"(hi) : "l"(v));
}
__device__ __forceinline__ unsigned long long fma2_(unsigned long long a,
                                                    unsigned long long b,
                                                    unsigned long long c) {
    unsigned long long d;
    asm("fma.rn.f32x2 %0, %1, %2, %3;" : "=l"(d) : "l"(a), "l"(b), "l"(c));
    return d;
}
__device__ __forceinline__ unsigned long long mul2_(unsigned long long a,
                                                    unsigned long long b) {
    unsigned long long d;
    asm("mul.rn.f32x2 %0, %1, %2;" : "=l"(d) : "l"(a), "l"(b));
    return d;
}

// ---------------------------------------------------------------------------
__global__ void init_p_kernel(const float* __restrict__ psf) {
    if (threadIdx.x == 0) {
        float p[5];
        for (int i = 0; i < 5; ++i) {
            float s = 0.f;
            for (int j = 0; j < 25; ++j) s += psf[i * 25 + j];
            p[i] = s;
            d_p[i] = s;
        }
        for (int i = 0; i < 9; ++i) {
            float s = 0.f;
            for (int a = 0; a < 5; ++a) {
                int b = i - a;
                if (b >= 0 && b < 5) s += p[a] * p[b];
            }
            d_q[i] = s;
        }
    }
}

// ===========================================================================
// S~ = conv_p2d(slices), computed ONCE per launch. spec dims (H,W mult of 32).
// ===========================================================================
template <int H, int W>
__global__ __launch_bounds__(256) void stilde_t(
    const float* __restrict__ slices, float* __restrict__ St) {
    constexpr int HW = H * W;
    __shared__ float sIn[36][38];
    __shared__ float sMid[36][33];

    const int i = blockIdx.z;
    const int x0 = blockIdx.x * 32, y0 = blockIdx.y * 32;
    const int tx = threadIdx.x, ty = threadIdx.y;
    const float p0 = d_p[0], p1 = d_p[1], p2 = d_p[2], p3 = d_p[3], p4 = d_p[4];
    const float* sl = slices + i * HW;

    // load 36x36 halo (zero outside image)
    #pragma unroll
    for (int k = 0; k < 5; ++k) {
        const int r = (k < 4) ? (ty + 8 * k) : (32 + ty);
        if (k == 4 && ty >= 4) break;
        const int gy = y0 - 2 + r;
        const bool okY = (unsigned)gy < (unsigned)H;
        #pragma unroll
        for (int b = 0; b < 2; ++b) {
            if (b == 1 && tx >= 4) break;
            const int c = b * 32 + tx;
            const int gx = x0 - 2 + c;
            sIn[r][c] = (okY && (unsigned)gx < (unsigned)W) ? sl[gy * W + gx] : 0.f;
        }
    }
    __syncthreads();

    // x-conv (36 rows x 32 cols)
    #pragma unroll
    for (int k = 0; k < 5; ++k) {
        const int r = (k < 4) ? (ty + 8 * k) : (32 + ty);
        if (k == 4 && ty >= 4) break;
        sMid[r][tx] = p0 * sIn[r][tx]     + p1 * sIn[r][tx + 1] + p2 * sIn[r][tx + 2]
                    + p3 * sIn[r][tx + 3] + p4 * sIn[r][tx + 4];
    }
    __syncthreads();

    // y-conv, store (32 x 32)
    float* Si = St + i * HW + y0 * W + x0;
    #pragma unroll
    for (int k = 0; k < 4; ++k) {
        const int r = ty + 8 * k;
        Si[r * W + tx] = p0 * sMid[r][tx]     + p1 * sMid[r + 1][tx]
                       + p2 * sMid[r + 2][tx] + p3 * sMid[r + 3][tx]
                       + p4 * sMid[r + 4][tx];
    }
}

// ===========================================================================
// fused_E v3 (spec): E = conv_p2d(conv_p2d(conv_z x) zeroed) - S~.
// Interior tiles: single 9-tap q conv (3 stages). Boundary tiles: 5-stage.
// 2 slices per block (shared 7-plane z window when stride==2).
// ===========================================================================
template <int D, int H, int W, int NS>
__global__ __launch_bounds__(256, 5) void fused_E3_t(
    const float* __restrict__ x, const float* __restrict__ St,
    float* __restrict__ E, const int* __restrict__ stridep) {
    constexpr int HW = H * W;
    __shared__ float bufZ[2][40][42];   // stage1 out; boundary: sF overlay (36x37)
    __shared__ float bufA[2][40][37];   // stage2 out; boundary: sB overlay (36x33)

    const int pr = blockIdx.z;
    const int stride = *stridep;
    const int iA = 2 * pr;
    const int ziA = iA * stride;
    const int x0 = blockIdx.x * 32, y0 = blockIdx.y * 32;
    const int tx = threadIdx.x, ty = threadIdx.y;

    const float p0 = d_p[0], p1 = d_p[1], p2 = d_p[2], p3 = d_p[3], p4 = d_p[4];

    const bool intXY = (x0 >= 4) && (x0 + 36 <= W) && (y0 >= 4) && (y0 + 36 <= H);
    const bool interior = (x0 >= 2) && (x0 + 34 <= W) && (y0 >= 2) && (y0 + 34 <= H);

    // ---- stage 1: z-combine both slices into bufZ (40x40, halo 4) ----
    if (stride == 2) {
        const int q0 = ziA - 2;                  // planes q0 .. q0+6
        const bool intZ = (q0 >= 0) && (ziA + 4 < D);
        if (intZ && intXY) {
            const float* base = x + q0 * HW + (y0 - 4) * W + (x0 - 4);
            #pragma unroll
            for (int k = 0; k < 5; ++k) {
                const int r = ty + 8 * k;
                const float* rowp = base + r * W;
                #pragma unroll
                for (int b = 0; b < 2; ++b) {
                    if (b == 1 && tx >= 8) break;
                    const int c = b * 32 + tx;
                    const float* col = rowp + c;
                    const float v0 = col[0],      v1 = col[HW],     v2 = col[2 * HW];
                    const float v3 = col[3 * HW], v4 = col[4 * HW], v5 = col[5 * HW];
                    const float v6 = col[6 * HW];
                    bufZ[0][r][c] = p0 * v0 + p1 * v1 + p2 * v2 + p3 * v3 + p4 * v4;
                    bufZ[1][r][c] = p0 * v2 + p1 * v3 + p2 * v4 + p3 * v5 + p4 * v6;
                }
            }
        } else {
            bool qok[7];
            #pragma unroll
            for (int j = 0; j < 7; ++j) qok[j] = (unsigned)(q0 + j) < (unsigned)D;
            #pragma unroll
            for (int k = 0; k < 5; ++k) {
                const int r = ty + 8 * k;
                const int gy = y0 - 4 + r;
                const bool okY = (unsigned)gy < (unsigned)H;
                #pragma unroll
                for (int b = 0; b < 2; ++b) {
                    if (b == 1 && tx >= 8) break;
                    const int c = b * 32 + tx;
                    const int gx = x0 - 4 + c;
                    const bool okXY = okY && (unsigned)gx < (unsigned)W;
                    const float* col = x + gy * W + gx;
                    float v[7];
                    #pragma unroll
                    for (int j = 0; j < 7; ++j)
                        v[j] = (okXY && qok[j]) ? col[(q0 + j) * HW] : 0.f;
                    bufZ[0][r][c] = p0 * v[0] + p1 * v[1] + p2 * v[2] + p3 * v[3] + p4 * v[4];
                    bufZ[1][r][c] = p0 * v[2] + p1 * v[3] + p2 * v[4] + p3 * v[5] + p4 * v[6];
                }
            }
        }
    } else {
        #pragma unroll
        for (int s = 0; s < 2; ++s) {
            const int zi = (iA + s) * stride;
            const int z0 = zi - 2;
            bool zok[5];
            #pragma unroll
            for (int j = 0; j < 5; ++j) zok[j] = (unsigned)(z0 + j) < (unsigned)D;
            #pragma unroll
            for (int k = 0; k < 5; ++k) {
                const int r = ty + 8 * k;
                const int gy = y0 - 4 + r;
                const bool okY = (unsigned)gy < (unsigned)H;
                #pragma unroll
                for (int b = 0; b < 2; ++b) {
                    if (b == 1 && tx >= 8) break;
                    const int c = b * 32 + tx;
                    const int gx = x0 - 4 + c;
                    const bool okXY = okY && (unsigned)gx < (unsigned)W;
                    const float* col = x + gy * W + gx;
                    float acc = 0.f;
                    if (okXY) {
                        if (zok[0]) acc = fmaf(p0, col[(z0 + 0) * HW], acc);
                        if (zok[1]) acc = fmaf(p1, col[(z0 + 1) * HW], acc);
                        if (zok[2]) acc = fmaf(p2, col[(z0 + 2) * HW], acc);
                        if (zok[3]) acc = fmaf(p3, col[(z0 + 3) * HW], acc);
                        if (zok[4]) acc = fmaf(p4, col[(z0 + 4) * HW], acc);
                    }
                    bufZ[s][r][c] = acc;
                }
            }
        }
    }
    __syncthreads();

    if (interior) {
        // ---- FAST PATH: single 9-tap conv q2d ----
        const float q0_ = d_q[0], q1_ = d_q[1], q2_ = d_q[2], q3_ = d_q[3];
        const float q4_ = d_q[4], q5_ = d_q[5], q6_ = d_q[6], q7_ = d_q[7];
        const float q8_ = d_q[8];

        #pragma unroll
        for (int s = 0; s < 2; ++s) {
            #pragma unroll
            for (int k = 0; k < 5; ++k) {
                const int r = ty + 8 * k;
                const float* zr = &bufZ[s][r][tx];
                bufA[s][r][tx] = q0_ * zr[0] + q1_ * zr[1] + q2_ * zr[2]
                               + q3_ * zr[3] + q4_ * zr[4] + q5_ * zr[5]
                               + q6_ * zr[6] + q7_ * zr[7] + q8_ * zr[8];
            }
        }
        __syncthreads();

        #pragma unroll
        for (int s = 0; s < 2; ++s) {
            float* Ei = E + (iA + s) * HW + y0 * W + x0;
            const float* Si = St + (iA + s) * HW + y0 * W + x0;
            #pragma unroll
            for (int k = 0; k < 4; ++k) {
                const int r = ty + 8 * k;
                float v = q0_ * bufA[s][r][tx]     + q1_ * bufA[s][r + 1][tx]
                        + q2_ * bufA[s][r + 2][tx] + q3_ * bufA[s][r + 3][tx]
                        + q4_ * bufA[s][r + 4][tx] + q5_ * bufA[s][r + 5][tx]
                        + q6_ * bufA[s][r + 6][tx] + q7_ * bufA[s][r + 7][tx]
                        + q8_ * bufA[s][r + 8][tx];
                Ei[r * W + tx] = v - Si[r * W + tx];
            }
        }
        return;
    }

    // ---- BOUNDARY PATH: 5-stage (F zeroed outside image), subtract S~ ----
    #pragma unroll
    for (int s = 0; s < 2; ++s) {
        #pragma unroll
        for (int k = 0; k < 5; ++k) {
            const int r = ty + 8 * k;
            bufA[s][r][tx] = p0 * bufZ[s][r][tx]     + p1 * bufZ[s][r][tx + 1]
                           + p2 * bufZ[s][r][tx + 2] + p3 * bufZ[s][r][tx + 3]
                           + p4 * bufZ[s][r][tx + 4];
            if (tx < 4) {
                const int c = 32 + tx;
                bufA[s][r][c] = p0 * bufZ[s][r][c]     + p1 * bufZ[s][r][c + 1]
                              + p2 * bufZ[s][r][c + 2] + p3 * bufZ[s][r][c + 3]
                              + p4 * bufZ[s][r][c + 4];
            }
        }
    }
    __syncthreads();

    {
        float (*sF0)[37] = (float (*)[37]) &bufZ[0][0][0];
        float (*sF1)[37] = (float (*)[37]) &bufZ[1][0][0];
        #pragma unroll
        for (int s = 0; s < 2; ++s) {
            float (*sF)[37] = s ? sF1 : sF0;
            #pragma unroll
            for (int k = 0; k < 5; ++k) {
                const int r = (k < 4) ? (ty + 8 * k) : (32 + ty);
                if (k == 4 && ty >= 4) break;
                const int gy = y0 - 2 + r;
                const bool okY = (unsigned)gy < (unsigned)H;
                #pragma unroll
                for (int b = 0; b < 2; ++b) {
                    if (b == 1 && tx >= 4) break;
                    const int c = b * 32 + tx;
                    const int gx = x0 - 2 + c;
                    float v = 0.f;
                    if (okY && (unsigned)gx < (unsigned)W) {
                        v = p0 * bufA[s][r][c]     + p1 * bufA[s][r + 1][c]
                          + p2 * bufA[s][r + 2][c] + p3 * bufA[s][r + 3][c]
                          + p4 * bufA[s][r + 4][c];
                    }
                    sF[r][c] = v;
                }
            }
        }
    }
    __syncthreads();

    {
        float (*sF0)[37] = (float (*)[37]) &bufZ[0][0][0];
        float (*sF1)[37] = (float (*)[37]) &bufZ[1][0][0];
        float (*sB0)[33] = (float (*)[33]) &bufA[0][0][0];
        float (*sB1)[33] = (float (*)[33]) &bufA[1][0][0];
        #pragma unroll
        for (int s = 0; s < 2; ++s) {
            float (*sF)[37] = s ? sF1 : sF0;
            float (*sB)[33] = s ? sB1 : sB0;
            #pragma unroll
            for (int k = 0; k < 5; ++k) {
                const int r = (k < 4) ? (ty + 8 * k) : (32 + ty);
                if (k == 4 && ty >= 4) break;
                sB[r][tx] = p0 * sF[r][tx]     + p1 * sF[r][tx + 1] + p2 * sF[r][tx + 2]
                          + p3 * sF[r][tx + 3] + p4 * sF[r][tx + 4];
            }
        }
    }
    __syncthreads();

    {
        float (*sB0)[33] = (float (*)[33]) &bufA[0][0][0];
        float (*sB1)[33] = (float (*)[33]) &bufA[1][0][0];
        #pragma unroll
        for (int s = 0; s < 2; ++s) {
            float (*sB)[33] = s ? sB1 : sB0;
            float* Ei = E + (iA + s) * HW + y0 * W + x0;
            const float* Si = St + (iA + s) * HW + y0 * W + x0;
            #pragma unroll
            for (int k = 0; k < 4; ++k) {
                const int r = ty + 8 * k;
                float v = p0 * sB[r][tx]     + p1 * sB[r + 1][tx]
                        + p2 * sB[r + 2][tx] + p3 * sB[r + 3][tx]
                        + p4 * sB[r + 4][tx];
                Ei[r * W + tx] = v - Si[r * W + tx];
            }
        }
    }
}

// ---------------------------------------------------------------------------
// update: 2 z per barrier, packed f32x2 regularizer (validated R7/R11 form,
// UPD_CHUNK back to 24).
template <int D, int H, int W, int NS>
__global__ __launch_bounds__(256, 4) void update2_t(
    const float* __restrict__ xin, const float* __restrict__ E,
    float* __restrict__ xout, const int* __restrict__ stridep, int do_relu) {
    constexpr int HW = H * W;
    __shared__ float s[4][10][36];

    const int x0 = blockIdx.x * 32, y0 = blockIdx.y * 8;
    const int zb = blockIdx.z * UPD_CHUNK;        // even
    const int tx = threadIdx.x, ty = threadIdx.y;
    const int tid = ty * 32 + tx;
    const int y = y0 + ty, x = x0 + tx;
    const int stride = *stridep;

    const float p0 = d_p[0], p1 = d_p[1], p2 = d_p[2], p3 = d_p[3], p4 = d_p[4];

    const float w1 = (float)(1.0 / (1.0 * 0.1 * 0.1));
    const float w2 = (float)(1.0 / (2.0 * 0.1 * 0.1));
    const float w3 = (float)(1.0 / (3.0 * 0.1 * 0.1));

    const int ly0 = tid / 34, lx0 = tid % 34;
    const int gy0 = y0 - 1 + ly0, gx0 = x0 - 1 + lx0;
    const bool ok0 = (unsigned)gy0 < (unsigned)H && (unsigned)gx0 < (unsigned)W;
    const int off0 = ok0 ? (gy0 * W + gx0) : 0;

    const int i1 = tid + 256;
    const bool has1 = (i1 < 340);
    const int ly1 = has1 ? i1 / 34 : 0, lx1 = has1 ? i1 % 34 : 0;
    const int gy1 = y0 - 1 + ly1, gx1 = x0 - 1 + lx1;
    const bool ok1 = has1 && (unsigned)gy1 < (unsigned)H && (unsigned)gx1 < (unsigned)W;
    const int off1 = ok1 ? (gy1 * W + gx1) : 0;

    auto loadPlane = [&](int z, int sl) {
        const bool zok = (unsigned)z < (unsigned)D;
        const int zo = (zok ? z : 0) * HW;
        s[sl][ly0][lx0] = (zok && ok0) ? xin[zo + off0] : 0.f;
        if (has1) s[sl][ly1][lx1] = (zok && ok1) ? xin[zo + off1] : 0.f;
    };

    loadPlane(zb - 1, (zb - 1) & 3);
    loadPlane(zb, zb & 3);
    __syncthreads();

    float A[9], B[9];
    {
        const int sm = (zb - 1) & 3, s0 = zb & 3;
        #pragma unroll
        for (int dy = 0; dy < 3; ++dy)
            #pragma unroll
            for (int dx = 0; dx < 3; ++dx) {
                A[dy * 3 + dx] = s[sm][ty + dy][tx + dx];
                B[dy * 3 + dx] = s[s0][ty + dy][tx + dx];
            }
    }

    const bool interior_xy = (y > 0 && y < H - 1 && x > 0 && x < W - 1);
    const int eo = y * W + x;
    const float* Ecol = E + eo;
    float* outcol = xout + eo;
    const float ALPHA = 0.5f;
    const float BETA = (float)(0.02 * 0.1 * 0.1);

    auto regTerm = [&](const float* Av, const float* Bv, const float* Cv) -> float {
        float greg = 0.f;
        const float v0 = Bv[4];
        #pragma unroll
        for (int j = 0; j < 9; ++j) {
            const int dy = j / 3 - 1, dx = j % 3 - 1;
            const int d2a = dy * dy + dx * dx + 1;
            const float wa = (d2a == 1) ? w1 : ((d2a == 2) ? w2 : w3);
            { float dv = v0 - Av[j]; float t = dv * wa; greg += t * rsqrtf(fmaf(dv, t, 1.0f)); }
            { float dv = v0 - Cv[j]; float t = dv * wa; greg += t * rsqrtf(fmaf(dv, t, 1.0f)); }
            if (j != 4) {
                const int d2b = dy * dy + dx * dx;
                const float wb = (d2b == 1) ? w1 : ((d2b == 2) ? w2 : w3);
                float dv = v0 - Bv[j]; float t = dv * wb;
                greg += t * rsqrtf(fmaf(dv, t, 1.0f));
            }
        }
        return greg;
    };

    const int zend = (zb + UPD_CHUNK < D) ? (zb + UPD_CHUNK) : D;

    if (stride == 2) {
        int h = zb >> 1;
        float eA = (h >= 1) ? Ecol[(h - 1) * HW] : 0.f;
        float eB = (h < NS) ? Ecol[h * HW] : 0.f;
        float eC = (h + 1 < NS) ? Ecol[(h + 1) * HW] : 0.f;

        for (int z = zb; z < zend; z += 2, ++h) {
            const int s1 = (z + 1) & 3, s2 = (z + 2) & 3;
            loadPlane(z + 1, s1);
            loadPlane(z + 2, s2);
            __syncthreads();

            float C1[9], C2[9];
            #pragma unroll
            for (int dy = 0; dy < 3; ++dy)
                #pragma unroll
                for (int dx = 0; dx < 3; ++dx) {
                    C1[dy * 3 + dx] = s[s1][ty + dy][tx + dx];
                    C2[dy * 3 + dx] = s[s2][ty + dy][tx + dx];
                }

            float ge = 0.f, go = 0.f;
            if (interior_xy) {
                const unsigned long long v0p  = pk2(B[4], C1[4]);
                const unsigned long long one2 = pk2(1.0f, 1.0f);
                const unsigned long long m12  = pk2(-1.0f, -1.0f);
                unsigned long long acc = pk2(0.0f, 0.0f);

                #pragma unroll
                for (int j = 0; j < 9; ++j) {
                    const int dy = j / 3 - 1, dx = j % 3 - 1;
                    const int d2 = dy * dy + dx * dx;
                    const float wa = (d2 == 0) ? w1 : ((d2 == 1) ? w2 : w3);
                    {
                        const unsigned long long np = pk2(A[j], B[j]);
                        const unsigned long long dv = fma2_(np, m12, v0p);
                        const unsigned long long wp = pk2(wa, wa);
                        const unsigned long long t  = mul2_(dv, wp);
                        const unsigned long long ar = fma2_(dv, t, one2);
                        float a0, a1; upk2(ar, a0, a1);
                        acc = fma2_(t, pk2(rsqrtf(a0), rsqrtf(a1)), acc);
                    }
                    {
                        const unsigned long long np = pk2(C1[j], C2[j]);
                        const unsigned long long dv = fma2_(np, m12, v0p);
                        const unsigned long long wp = pk2(wa, wa);
                        const unsigned long long t  = mul2_(dv, wp);
                        const unsigned long long ar = fma2_(dv, t, one2);
                        float a0, a1; upk2(ar, a0, a1);
                        acc = fma2_(t, pk2(rsqrtf(a0), rsqrtf(a1)), acc);
                    }
                    if (j != 4) {
                        const float wb = (d2 == 1) ? w1 : w2;
                        const unsigned long long np = pk2(B[j], C1[j]);
                        const unsigned long long dv = fma2_(np, m12, v0p);
                        const unsigned long long wp = pk2(wb, wb);
                        const unsigned long long t  = mul2_(dv, wp);
                        const unsigned long long ar = fma2_(dv, t, one2);
                        float a0, a1; upk2(ar, a0, a1);
                        acc = fma2_(t, pk2(rsqrtf(a0), rsqrtf(a1)), acc);
                    }
                }
                upk2(acc, ge, go);
                if (z == 0) ge = 0.f;
                if (z + 1 == D - 1) go = 0.f;
            }

            {
                float gd = fmaf(p0, eA, fmaf(p2, eB, p4 * eC));
                float xn = B[4] - ALPHA * (gd + BETA * ge);
                if (do_relu) xn = fmaxf(xn, 0.f);
                outcol[z * HW] = xn;
            }
            {
                float gd = fmaf(p1, eB, p3 * eC);
                float xn = C1[4] - ALPHA * (gd + BETA * go);
                if (do_relu) xn = fmaxf(xn, 0.f);
                outcol[(z + 1) * HW] = xn;
            }

            #pragma unroll
            for (int j = 0; j < 9; ++j) { A[j] = C1[j]; B[j] = C2[j]; }
            eA = eB; eB = eC;
            eC = (h + 2 < NS) ? Ecol[(h + 2) * HW] : 0.f;
        }
    } else {
        const float pz[5] = {p0, p1, p2, p3, p4};
        for (int z = zb; z < zend; ++z) {
            const int sl = (z + 1) & 3;
            loadPlane(z + 1, sl);
            __syncthreads();
            float C[9];
            #pragma unroll
            for (int dy = 0; dy < 3; ++dy)
                #pragma unroll
                for (int dx = 0; dx < 3; ++dx)
                    C[dy * 3 + dx] = s[sl][ty + dy][tx + dx];

            float gd = 0.f;
            #pragma unroll
            for (int dz = 0; dz < 5; ++dz) {
                int zz = z + dz - 2;
                if ((unsigned)zz < (unsigned)D && (zz % stride) == 0) {
                    int pi = zz / stride;
                    if (pi < NS) gd = fmaf(pz[dz], Ecol[pi * HW], gd);
                }
            }
            float greg = 0.f;
            if (interior_xy && z > 0 && z < D - 1) greg = regTerm(A, B, C);
            float xn = B[4] - ALPHA * (gd + BETA * greg);
            if (do_relu) xn = fmaxf(xn, 0.f);
            outcol[z * HW] = xn;
            #pragma unroll
            for (int j = 0; j < 9; ++j) { A[j] = B[j]; B[j] = C[j]; }
        }
    }
}

// ===========================================================================
// Generic fallback kernels (runtime dims) — validated in R4/R5.
// ===========================================================================

__global__ __launch_bounds__(256) void fused_E_gen(
    const float* __restrict__ x, const float* __restrict__ slices,
    float* __restrict__ E, const int* __restrict__ stridep,
    int D, int H, int W, int n_slices) {
    __shared__ float sZ[40][44];
    __shared__ float sA[40][36];
    __shared__ float sF[36][36];
    __shared__ float sB[36][33];

    const int i = blockIdx.z;
    const int zi = i * (*stridep);
    const int x0 = blockIdx.x * 32, y0 = blockIdx.y * 32;
    const int tx = threadIdx.x, ty = threadIdx.y;
    const size_t HW = (size_t)H * W;

    const float p0 = d_p[0], p1 = d_p[1], p2 = d_p[2], p3 = d_p[3], p4 = d_p[4];

    {
        const int z0 = zi - 2;
        const bool zok0 = (z0 >= 0), zok1 = (z0 + 1 >= 0);
        const bool zok2 = (z0 + 2 >= 0) && (z0 + 2 < D);
        const bool zok3 = (z0 + 3 < D), zok4 = (z0 + 4 < D);
        #pragma unroll
        for (int k = 0; k < 5; ++k) {
            const int r = ty + 8 * k;
            const int gy = y0 - 4 + r;
            const bool okY = (unsigned)gy < (unsigned)H;
            #pragma unroll
            for (int b = 0; b < 2; ++b) {
                const int c = b * 32 + tx;
                if (b == 1 && tx >= 8) break;
                const int gx = x0 - 4 + c;
                float acc = 0.f;
                if (okY && (unsigned)gx < (unsigned)W) {
                    const float* col = x + (size_t)gy * W + gx + (size_t)z0 * HW;
                    if (zok0) acc = fmaf(p0, col[0], acc);
                    if (zok1) acc = fmaf(p1, col[HW], acc);
                    if (zok2) acc = fmaf(p2, col[2 * HW], acc);
                    if (zok3) acc = fmaf(p3, col[3 * HW], acc);
                    if (zok4) acc = fmaf(p4, col[4 * HW], acc);
                }
                sZ[r][c] = acc;
            }
        }
    }
    __syncthreads();

    #pragma unroll
    for (int k = 0; k < 5; ++k) {
        const int r = ty + 8 * k;
        sA[r][tx] = p0 * sZ[r][tx]     + p1 * sZ[r][tx + 1] + p2 * sZ[r][tx + 2]
                  + p3 * sZ[r][tx + 3] + p4 * sZ[r][tx + 4];
        if (tx < 4) {
            const int c = 32 + tx;
            sA[r][c] = p0 * sZ[r][c]     + p1 * sZ[r][c + 1] + p2 * sZ[r][c + 2]
                     + p3 * sZ[r][c + 3] + p4 * sZ[r][c + 4];
        }
    }
    __syncthreads();

    {
        const float* sl = slices + (size_t)i * HW;
        #pragma unroll
        for (int k = 0; k < 5; ++k) {
            const int r = (k < 4) ? (ty + 8 * k) : (32 + ty);
            if (k == 4 && ty >= 4) break;
            const int gy = y0 - 2 + r;
            const bool okY = (unsigned)gy < (unsigned)H;
            #pragma unroll
            for (int b = 0; b < 2; ++b) {
                const int c = b * 32 + tx;
                if (b == 1 && tx >= 4) break;
                const int gx = x0 - 2 + c;
                float v = 0.f;
                if (okY && (unsigned)gx < (unsigned)W) {
                    v = p0 * sA[r][c]     + p1 * sA[r + 1][c] + p2 * sA[r + 2][c]
                      + p3 * sA[r + 3][c] + p4 * sA[r + 4][c]
                      - sl[(size_t)gy * W + gx];
                }
                sF[r][c] = v;
            }
        }
    }
    __syncthreads();

    #pragma unroll
    for (int k = 0; k < 5; ++k) {
        const int r = (k < 4) ? (ty + 8 * k) : (32 + ty);
        if (k == 4 && ty >= 4) break;
        sB[r][tx] = p0 * sF[r][tx]     + p1 * sF[r][tx + 1] + p2 * sF[r][tx + 2]
                  + p3 * sF[r][tx + 3] + p4 * sF[r][tx + 4];
    }
    __syncthreads();

    {
        float* Ei = E + (size_t)i * HW;
        #pragma unroll
        for (int k = 0; k < 4; ++k) {
            const int r = ty + 8 * k;
            const int gy = y0 + r, gx = x0 + tx;
            if (gy < H && gx < W) {
                Ei[(size_t)gy * W + gx] =
                      p0 * sB[r][tx]     + p1 * sB[r + 1][tx] + p2 * sB[r + 2][tx]
                    + p3 * sB[r + 3][tx] + p4 * sB[r + 4][tx];
            }
        }
    }
}

__global__ __launch_bounds__(256, 4) void update_gen(
    const float* __restrict__ xin, const float* __restrict__ E,
    float* __restrict__ xout, const int* __restrict__ stridep,
    int n_slices, int D, int H, int W, int do_relu) {
    __shared__ float s[3][10][36];

    const int x0 = blockIdx.x * 32, y0 = blockIdx.y * 8;
    const int zb = blockIdx.z * UPD_CHUNK;
    const int tx = threadIdx.x, ty = threadIdx.y;
    const int tid = ty * 32 + tx;
    const size_t HW = (size_t)H * W;
    const int y = y0 + ty, x = x0 + tx;
    const int stride = *stridep;

    const float p0 = d_p[0], p1 = d_p[1], p2 = d_p[2], p3 = d_p[3], p4 = d_p[4];
    const float pz[5] = {p0, p1, p2, p3, p4};
    const float w1 = (float)(1.0 / (1.0 * 0.1 * 0.1));
    const float w2 = (float)(1.0 / (2.0 * 0.1 * 0.1));
    const float w3 = (float)(1.0 / (3.0 * 0.1 * 0.1));

    const int ly0 = tid / 34, lx0 = tid % 34;
    const int gy0 = y0 - 1 + ly0, gx0 = x0 - 1 + lx0;
    const bool ok0 = (unsigned)gy0 < (unsigned)H && (unsigned)gx0 < (unsigned)W;
    const size_t off0 = ok0 ? ((size_t)gy0 * W + gx0) : 0;
    const int i1 = tid + 256;
    const bool has1 = (i1 < 340);
    const int ly1 = has1 ? i1 / 34 : 0, lx1 = has1 ? i1 % 34 : 0;
    const int gy1 = y0 - 1 + ly1, gx1 = x0 - 1 + lx1;
    const bool ok1 = has1 && (unsigned)gy1 < (unsigned)H && (unsigned)gx1 < (unsigned)W;
    const size_t off1 = ok1 ? ((size_t)gy1 * W + gx1) : 0;

    auto loadPlane = [&](int z, int sl) {
        const bool zok = (unsigned)z < (unsigned)D;
        const size_t zo = (size_t)(zok ? z : 0) * HW;
        s[sl][ly0][lx0] = (zok && ok0) ? xin[zo + off0] : 0.f;
        if (has1) s[sl][ly1][lx1] = (zok && ok1) ? xin[zo + off1] : 0.f;
    };

    const int sl_m1 = ((zb - 1) % 3 + 3) % 3;
    const int sl_0  = zb % 3;
    loadPlane(zb - 1, sl_m1);
    loadPlane(zb, sl_0);
    __syncthreads();

    float A[9], B[9];
    #pragma unroll
    for (int dy = 0; dy < 3; ++dy)
        #pragma unroll
        for (int dx = 0; dx < 3; ++dx) {
            A[dy * 3 + dx] = s[sl_m1][ty + dy][tx + dx];
            B[dy * 3 + dx] = s[sl_0][ty + dy][tx + dx];
        }

    const bool interior_xy = (y > 0 && y < H - 1 && x > 0 && x < W - 1);
    const size_t eo = (size_t)y * W + x;
    const float* Ecol = E + eo;
    float* outcol = xout + eo;
    const float ALPHA = 0.5f;
    const float BETA = (float)(0.02 * 0.1 * 0.1);

    int zend = zb + UPD_CHUNK;
    if (zend > D) zend = D;

    for (int z = zb; z < zend; ++z) {
        const int sl = (z + 1) % 3;
        loadPlane(z + 1, sl);
        __syncthreads();

        float C[9];
        #pragma unroll
        for (int dy = 0; dy < 3; ++dy)
            #pragma unroll
            for (int dx = 0; dx < 3; ++dx)
                C[dy * 3 + dx] = s[sl][ty + dy][tx + dx];

        const float v0 = B[4];
        float gd = 0.f;
        #pragma unroll
        for (int dz = 0; dz < 5; ++dz) {
            int zz = z + dz - 2;
            if ((unsigned)zz < (unsigned)D && (zz % stride) == 0) {
                int pi = zz / stride;
                if (pi < n_slices) gd = fmaf(pz[dz], Ecol[(size_t)pi * HW], gd);
            }
        }

        float greg = 0.f;
        if (interior_xy && z > 0 && z < D - 1) {
            #pragma unroll
            for (int j = 0; j < 9; ++j) {
                const int dy = j / 3 - 1, dx = j % 3 - 1;
                const int d2a = dy * dy + dx * dx + 1;
                const float wa = (d2a == 1) ? w1 : ((d2a == 2) ? w2 : w3);
                { float dv = v0 - A[j]; float t = dv * wa; greg += t * rsqrtf(fmaf(dv, t, 1.0f)); }
                { float dv = v0 - C[j]; float t = dv * wa; greg += t * rsqrtf(fmaf(dv, t, 1.0f)); }
                if (j != 4) {
                    const int d2b = dy * dy + dx * dx;
                    const float wb = (d2b == 1) ? w1 : ((d2b == 2) ? w2 : w3);
                    float dv = v0 - B[j]; float t = dv * wb;
                    greg += t * rsqrtf(fmaf(dv, t, 1.0f));
                }
            }
        }

        float xn = v0 - ALPHA * (gd + BETA * greg);
        if (do_relu) xn = fmaxf(xn, 0.f);
        outcol[(size_t)z * HW] = xn;

        #pragma unroll
        for (int j = 0; j < 9; ++j) { A[j] = B[j]; B[j] = C[j]; }
    }
}

// ---------------------------------------------------------------------------
extern "C" void kernel_launch(void* const* d_in, const int* in_sizes, int n_in,
                              void* d_out, int out_size) {
    const float* slices = (const float*)d_in[1];
    const float* volume = (const float*)d_in[2];
    const float* psf    = (const float*)d_in[3];
    const int* stridep  = (const int*)d_in[4];

    int D = (int)lround(cbrt((double)out_size));   // 192
    int H = D, W = D;
    int n_slices = in_sizes[1] / (H * W);

    float *pE, *pA, *pB;
    cudaGetSymbolAddress((void**)&pE, d_E);
    cudaGetSymbolAddress((void**)&pA, d_A);
    cudaGetSymbolAddress((void**)&pB, d_B);

    init_p_kernel<<<1, 32>>>(psf);

    const bool spec = (D == 192 && H == 192 && W == 192 && n_slices == 96);

    dim3 blkE(32, 8, 1);
    dim3 grid_E2((W + 31) / 32, (H + 31) / 32, n_slices / 2);
    dim3 grid_E((W + 31) / 32, (H + 31) / 32, n_slices);
    dim3 blkU(32, 8, 1);
    dim3 grid_up((W + 31) / 32, (H + 7) / 8, (D + UPD_CHUNK - 1) / UPD_CHUNK);

    if (spec) {
        // one-time: S~ = conv_p2d(slices) into pB
        stilde_t<192, 192><<<dim3(6, 6, 96), blkE>>>(slices, pB);
        for (int it = 0; it < N_ITER; ++it) {
            const float* xin = (it == 0) ? volume
                                         : ((it & 1) ? pA : (const float*)d_out);
            float* xout = (it & 1) ? (float*)d_out : pA;
            int do_relu = (it == N_ITER - 1) ? 1 : 0;
            fused_E3_t<192, 192, 192, 96><<<grid_E2, blkE>>>(xin, pB, pE, stridep);
            update2_t<192, 192, 192, 96><<<grid_up, blkU>>>(xin, pE, xout, stridep, do_relu);
        }
    } else {
        for (int it = 0; it < N_ITER; ++it) {
            const float* xin = (it == 0) ? volume : ((it & 1) ? pA : pB);
            float* xout = (it == N_ITER - 1) ? (float*)d_out
                                             : ((it & 1) ? pB : pA);
            int do_relu = (it == N_ITER - 1) ? 1 : 0;
            fused_E_gen<<<grid_E, blkE>>>(xin, slices, pE, stridep, D, H, W, n_slices);
            update_gen<<<grid_up, blkU>>>(xin, pE, xout, stridep, n_slices, D, H, W, do_relu);
        }
    }
}

// round 14
// speedup vs baseline: 1.6712x; 1.1065x over previous
#include <cuda_runtime.h>
#include <math.h>

#define N_ITER 10
#define UPD_CHUNK 24

static __device__ float d_p[5];                     // separable 1D psf
static __device__ float d_q[9];                     // q = p (*) p  (9-tap)
static __device__ float d_E[96 * 192 * 192];        // conv_xy(residual) planes
static __device__ float d_A[192 * 192 * 192];       // ping
static __device__ float d_B[192 * 192 * 192];       // spec: S~ ; gen: pong

// ---------------------------------------------------------------------------
// packed f32x2 helpers (Blackwell)
// ---------------------------------------------------------------------------
__device__ __forceinline__ unsigned long long pk2(float lo, float hi) {
    unsigned long long r;
    asm("mov.b64 %0, {%1, %2};" : "=l"(r) : "f"(lo), "f"(hi));
    return r;
}
__device__ __forceinline__ void upk2(unsigned long long v, float& lo, float& hi) {
    asm("mov.b64 {%0, %1}, %2;" : "=f"(lo), "=f"(hi) : "l"(v));
}
__device__ __forceinline__ unsigned long long fma2_(unsigned long long a,
                                                    unsigned long long b,
                                                    unsigned long long c) {
    unsigned long long d;
    asm("fma.rn.f32x2 %0, %1, %2, %3;" : "=l"(d) : "l"(a), "l"(b), "l"(c));
    return d;
}
__device__ __forceinline__ unsigned long long mul2_(unsigned long long a,
                                                    unsigned long long b) {
    unsigned long long d;
    asm("mul.rn.f32x2 %0, %1, %2;" : "=l"(d) : "l"(a), "l"(b));
    return d;
}

// ---------------------------------------------------------------------------
__global__ void init_p_kernel(const float* __restrict__ psf) {
    if (threadIdx.x == 0) {
        float p[5];
        for (int i = 0; i < 5; ++i) {
            float s = 0.f;
            for (int j = 0; j < 25; ++j) s += psf[i * 25 + j];
            p[i] = s;
            d_p[i] = s;
        }
        for (int i = 0; i < 9; ++i) {
            float s = 0.f;
            for (int a = 0; a < 5; ++a) {
                int b = i - a;
                if (b >= 0 && b < 5) s += p[a] * p[b];
            }
            d_q[i] = s;
        }
    }
}

// ===========================================================================
// S~ = conv_p2d(slices), computed ONCE per launch. spec dims (H,W mult of 32).
// ===========================================================================
template <int H, int W>
__global__ __launch_bounds__(256) void stilde_t(
    const float* __restrict__ slices, float* __restrict__ St) {
    constexpr int HW = H * W;
    __shared__ float sIn[36][38];
    __shared__ float sMid[36][33];

    const int i = blockIdx.z;
    const int x0 = blockIdx.x * 32, y0 = blockIdx.y * 32;
    const int tx = threadIdx.x, ty = threadIdx.y;
    const float p0 = d_p[0], p1 = d_p[1], p2 = d_p[2], p3 = d_p[3], p4 = d_p[4];
    const float* sl = slices + i * HW;

    #pragma unroll
    for (int k = 0; k < 5; ++k) {
        const int r = (k < 4) ? (ty + 8 * k) : (32 + ty);
        if (k == 4 && ty >= 4) break;
        const int gy = y0 - 2 + r;
        const bool okY = (unsigned)gy < (unsigned)H;
        #pragma unroll
        for (int b = 0; b < 2; ++b) {
            if (b == 1 && tx >= 4) break;
            const int c = b * 32 + tx;
            const int gx = x0 - 2 + c;
            sIn[r][c] = (okY && (unsigned)gx < (unsigned)W) ? sl[gy * W + gx] : 0.f;
        }
    }
    __syncthreads();

    #pragma unroll
    for (int k = 0; k < 5; ++k) {
        const int r = (k < 4) ? (ty + 8 * k) : (32 + ty);
        if (k == 4 && ty >= 4) break;
        sMid[r][tx] = p0 * sIn[r][tx]     + p1 * sIn[r][tx + 1] + p2 * sIn[r][tx + 2]
                    + p3 * sIn[r][tx + 3] + p4 * sIn[r][tx + 4];
    }
    __syncthreads();

    float* Si = St + i * HW + y0 * W + x0;
    #pragma unroll
    for (int k = 0; k < 4; ++k) {
        const int r = ty + 8 * k;
        Si[r * W + tx] = p0 * sMid[r][tx]     + p1 * sMid[r + 1][tx]
                       + p2 * sMid[r + 2][tx] + p3 * sMid[r + 3][tx]
                       + p4 * sMid[r + 4][tx];
    }
}

// ===========================================================================
// fused_E v3 (spec) — unchanged from validated R12/R13.
// ===========================================================================
template <int D, int H, int W, int NS>
__global__ __launch_bounds__(256, 5) void fused_E3_t(
    const float* __restrict__ x, const float* __restrict__ St,
    float* __restrict__ E, const int* __restrict__ stridep) {
    constexpr int HW = H * W;
    __shared__ float bufZ[2][40][42];
    __shared__ float bufA[2][40][37];

    const int pr = blockIdx.z;
    const int stride = *stridep;
    const int iA = 2 * pr;
    const int ziA = iA * stride;
    const int x0 = blockIdx.x * 32, y0 = blockIdx.y * 32;
    const int tx = threadIdx.x, ty = threadIdx.y;

    const float p0 = d_p[0], p1 = d_p[1], p2 = d_p[2], p3 = d_p[3], p4 = d_p[4];

    const bool intXY = (x0 >= 4) && (x0 + 36 <= W) && (y0 >= 4) && (y0 + 36 <= H);
    const bool interior = (x0 >= 2) && (x0 + 34 <= W) && (y0 >= 2) && (y0 + 34 <= H);

    if (stride == 2) {
        const int q0 = ziA - 2;
        const bool intZ = (q0 >= 0) && (ziA + 4 < D);
        if (intZ && intXY) {
            const float* base = x + q0 * HW + (y0 - 4) * W + (x0 - 4);
            #pragma unroll
            for (int k = 0; k < 5; ++k) {
                const int r = ty + 8 * k;
                const float* rowp = base + r * W;
                #pragma unroll
                for (int b = 0; b < 2; ++b) {
                    if (b == 1 && tx >= 8) break;
                    const int c = b * 32 + tx;
                    const float* col = rowp + c;
                    const float v0 = col[0],      v1 = col[HW],     v2 = col[2 * HW];
                    const float v3 = col[3 * HW], v4 = col[4 * HW], v5 = col[5 * HW];
                    const float v6 = col[6 * HW];
                    bufZ[0][r][c] = p0 * v0 + p1 * v1 + p2 * v2 + p3 * v3 + p4 * v4;
                    bufZ[1][r][c] = p0 * v2 + p1 * v3 + p2 * v4 + p3 * v5 + p4 * v6;
                }
            }
        } else {
            bool qok[7];
            #pragma unroll
            for (int j = 0; j < 7; ++j) qok[j] = (unsigned)(q0 + j) < (unsigned)D;
            #pragma unroll
            for (int k = 0; k < 5; ++k) {
                const int r = ty + 8 * k;
                const int gy = y0 - 4 + r;
                const bool okY = (unsigned)gy < (unsigned)H;
                #pragma unroll
                for (int b = 0; b < 2; ++b) {
                    if (b == 1 && tx >= 8) break;
                    const int c = b * 32 + tx;
                    const int gx = x0 - 4 + c;
                    const bool okXY = okY && (unsigned)gx < (unsigned)W;
                    const float* col = x + gy * W + gx;
                    float v[7];
                    #pragma unroll
                    for (int j = 0; j < 7; ++j)
                        v[j] = (okXY && qok[j]) ? col[(q0 + j) * HW] : 0.f;
                    bufZ[0][r][c] = p0 * v[0] + p1 * v[1] + p2 * v[2] + p3 * v[3] + p4 * v[4];
                    bufZ[1][r][c] = p0 * v[2] + p1 * v[3] + p2 * v[4] + p3 * v[5] + p4 * v[6];
                }
            }
        }
    } else {
        #pragma unroll
        for (int s = 0; s < 2; ++s) {
            const int zi = (iA + s) * stride;
            const int z0 = zi - 2;
            bool zok[5];
            #pragma unroll
            for (int j = 0; j < 5; ++j) zok[j] = (unsigned)(z0 + j) < (unsigned)D;
            #pragma unroll
            for (int k = 0; k < 5; ++k) {
                const int r = ty + 8 * k;
                const int gy = y0 - 4 + r;
                const bool okY = (unsigned)gy < (unsigned)H;
                #pragma unroll
                for (int b = 0; b < 2; ++b) {
                    if (b == 1 && tx >= 8) break;
                    const int c = b * 32 + tx;
                    const int gx = x0 - 4 + c;
                    const bool okXY = okY && (unsigned)gx < (unsigned)W;
                    const float* col = x + gy * W + gx;
                    float acc = 0.f;
                    if (okXY) {
                        if (zok[0]) acc = fmaf(p0, col[(z0 + 0) * HW], acc);
                        if (zok[1]) acc = fmaf(p1, col[(z0 + 1) * HW], acc);
                        if (zok[2]) acc = fmaf(p2, col[(z0 + 2) * HW], acc);
                        if (zok[3]) acc = fmaf(p3, col[(z0 + 3) * HW], acc);
                        if (zok[4]) acc = fmaf(p4, col[(z0 + 4) * HW], acc);
                    }
                    bufZ[s][r][c] = acc;
                }
            }
        }
    }
    __syncthreads();

    if (interior) {
        const float q0_ = d_q[0], q1_ = d_q[1], q2_ = d_q[2], q3_ = d_q[3];
        const float q4_ = d_q[4], q5_ = d_q[5], q6_ = d_q[6], q7_ = d_q[7];
        const float q8_ = d_q[8];

        #pragma unroll
        for (int s = 0; s < 2; ++s) {
            #pragma unroll
            for (int k = 0; k < 5; ++k) {
                const int r = ty + 8 * k;
                const float* zr = &bufZ[s][r][tx];
                bufA[s][r][tx] = q0_ * zr[0] + q1_ * zr[1] + q2_ * zr[2]
                               + q3_ * zr[3] + q4_ * zr[4] + q5_ * zr[5]
                               + q6_ * zr[6] + q7_ * zr[7] + q8_ * zr[8];
            }
        }
        __syncthreads();

        #pragma unroll
        for (int s = 0; s < 2; ++s) {
            float* Ei = E + (iA + s) * HW + y0 * W + x0;
            const float* Si = St + (iA + s) * HW + y0 * W + x0;
            #pragma unroll
            for (int k = 0; k < 4; ++k) {
                const int r = ty + 8 * k;
                float v = q0_ * bufA[s][r][tx]     + q1_ * bufA[s][r + 1][tx]
                        + q2_ * bufA[s][r + 2][tx] + q3_ * bufA[s][r + 3][tx]
                        + q4_ * bufA[s][r + 4][tx] + q5_ * bufA[s][r + 5][tx]
                        + q6_ * bufA[s][r + 6][tx] + q7_ * bufA[s][r + 7][tx]
                        + q8_ * bufA[s][r + 8][tx];
                Ei[r * W + tx] = v - Si[r * W + tx];
            }
        }
        return;
    }

    #pragma unroll
    for (int s = 0; s < 2; ++s) {
        #pragma unroll
        for (int k = 0; k < 5; ++k) {
            const int r = ty + 8 * k;
            bufA[s][r][tx] = p0 * bufZ[s][r][tx]     + p1 * bufZ[s][r][tx + 1]
                           + p2 * bufZ[s][r][tx + 2] + p3 * bufZ[s][r][tx + 3]
                           + p4 * bufZ[s][r][tx + 4];
            if (tx < 4) {
                const int c = 32 + tx;
                bufA[s][r][c] = p0 * bufZ[s][r][c]     + p1 * bufZ[s][r][c + 1]
                              + p2 * bufZ[s][r][c + 2] + p3 * bufZ[s][r][c + 3]
                              + p4 * bufZ[s][r][c + 4];
            }
        }
    }
    __syncthreads();

    {
        float (*sF0)[37] = (float (*)[37]) &bufZ[0][0][0];
        float (*sF1)[37] = (float (*)[37]) &bufZ[1][0][0];
        #pragma unroll
        for (int s = 0; s < 2; ++s) {
            float (*sF)[37] = s ? sF1 : sF0;
            #pragma unroll
            for (int k = 0; k < 5; ++k) {
                const int r = (k < 4) ? (ty + 8 * k) : (32 + ty);
                if (k == 4 && ty >= 4) break;
                const int gy = y0 - 2 + r;
                const bool okY = (unsigned)gy < (unsigned)H;
                #pragma unroll
                for (int b = 0; b < 2; ++b) {
                    if (b == 1 && tx >= 4) break;
                    const int c = b * 32 + tx;
                    const int gx = x0 - 2 + c;
                    float v = 0.f;
                    if (okY && (unsigned)gx < (unsigned)W) {
                        v = p0 * bufA[s][r][c]     + p1 * bufA[s][r + 1][c]
                          + p2 * bufA[s][r + 2][c] + p3 * bufA[s][r + 3][c]
                          + p4 * bufA[s][r + 4][c];
                    }
                    sF[r][c] = v;
                }
            }
        }
    }
    __syncthreads();

    {
        float (*sF0)[37] = (float (*)[37]) &bufZ[0][0][0];
        float (*sF1)[37] = (float (*)[37]) &bufZ[1][0][0];
        float (*sB0)[33] = (float (*)[33]) &bufA[0][0][0];
        float (*sB1)[33] = (float (*)[33]) &bufA[1][0][0];
        #pragma unroll
        for (int s = 0; s < 2; ++s) {
            float (*sF)[37] = s ? sF1 : sF0;
            float (*sB)[33] = s ? sB1 : sB0;
            #pragma unroll
            for (int k = 0; k < 5; ++k) {
                const int r = (k < 4) ? (ty + 8 * k) : (32 + ty);
                if (k == 4 && ty >= 4) break;
                sB[r][tx] = p0 * sF[r][tx]     + p1 * sF[r][tx + 1] + p2 * sF[r][tx + 2]
                          + p3 * sF[r][tx + 3] + p4 * sF[r][tx + 4];
            }
        }
    }
    __syncthreads();

    {
        float (*sB0)[33] = (float (*)[33]) &bufA[0][0][0];
        float (*sB1)[33] = (float (*)[33]) &bufA[1][0][0];
        #pragma unroll
        for (int s = 0; s < 2; ++s) {
            float (*sB)[33] = s ? sB1 : sB0;
            float* Ei = E + (iA + s) * HW + y0 * W + x0;
            const float* Si = St + (iA + s) * HW + y0 * W + x0;
            #pragma unroll
            for (int k = 0; k < 4; ++k) {
                const int r = ty + 8 * k;
                float v = p0 * sB[r][tx]     + p1 * sB[r + 1][tx]
                        + p2 * sB[r + 2][tx] + p3 * sB[r + 3][tx]
                        + p4 * sB[r + 4][tx];
                Ei[r * W + tx] = v - Si[r * W + tx];
            }
        }
    }
}

// ===========================================================================
// update v3 (spec): float2-interleaved z-pair smem ring (3 slots), operands
// read per-class from LDS.64 (no persistent register arrays), occupancy 5.
// Pair k holds planes (zb-1+2k [lo], zb+2k [hi]).
// ===========================================================================
template <int D, int H, int W, int NS>
__global__ __launch_bounds__(256, 5) void update3_t(
    const float* __restrict__ xin, const float* __restrict__ E,
    float* __restrict__ xout, const int* __restrict__ stridep, int do_relu) {
    constexpr int HW = H * W;
    __shared__ float2 sp[3][10][36];

    const int x0 = blockIdx.x * 32, y0 = blockIdx.y * 8;
    const int zb = blockIdx.z * UPD_CHUNK;        // even
    const int tx = threadIdx.x, ty = threadIdx.y;
    const int tid = ty * 32 + tx;
    const int y = y0 + ty, x = x0 + tx;
    const int stride = *stridep;

    const float p0 = d_p[0], p1 = d_p[1], p2 = d_p[2], p3 = d_p[3], p4 = d_p[4];

    const float w1 = (float)(1.0 / (1.0 * 0.1 * 0.1));
    const float w2 = (float)(1.0 / (2.0 * 0.1 * 0.1));
    const float w3 = (float)(1.0 / (3.0 * 0.1 * 0.1));

    // hoisted cooperative-load geometry (10*34 = 340 slots)
    const int ly0 = tid / 34, lx0 = tid % 34;
    const int gy0 = y0 - 1 + ly0, gx0 = x0 - 1 + lx0;
    const bool ok0 = (unsigned)gy0 < (unsigned)H && (unsigned)gx0 < (unsigned)W;
    const int off0 = ok0 ? (gy0 * W + gx0) : 0;

    const int i1 = tid + 256;
    const bool has1 = (i1 < 340);
    const int ly1 = has1 ? i1 / 34 : 0, lx1 = has1 ? i1 % 34 : 0;
    const int gy1 = y0 - 1 + ly1, gx1 = x0 - 1 + lx1;
    const bool ok1 = has1 && (unsigned)gy1 < (unsigned)H && (unsigned)gx1 < (unsigned)W;
    const int off1 = ok1 ? (gy1 * W + gx1) : 0;

    auto loadPair = [&](int k, int buf) {
        const int za = zb - 1 + 2 * k, zbp = zb + 2 * k;
        const bool zaok = (unsigned)za < (unsigned)D;
        const bool zbok = (unsigned)zbp < (unsigned)D;
        const int zoA = (zaok ? za : 0) * HW;
        const int zoB = (zbok ? zbp : 0) * HW;
        {
            float a = (zaok && ok0) ? xin[zoA + off0] : 0.f;
            float b = (zbok && ok0) ? xin[zoB + off0] : 0.f;
            sp[buf][ly0][lx0] = make_float2(a, b);
        }
        if (has1) {
            float a = (zaok && ok1) ? xin[zoA + off1] : 0.f;
            float b = (zbok && ok1) ? xin[zoB + off1] : 0.f;
            sp[buf][ly1][lx1] = make_float2(a, b);
        }
    };

    loadPair(0, 0);
    loadPair(1, 1);
    __syncthreads();

    const bool interior_xy = (y > 0 && y < H - 1 && x > 0 && x < W - 1);
    const int eo = y * W + x;
    const float* Ecol = E + eo;
    float* outcol = xout + eo;
    const float ALPHA = 0.5f;
    const float BETA = (float)(0.02 * 0.1 * 0.1);

    const unsigned long long w1p = pk2(w1, w1);
    const unsigned long long w2p = pk2(w2, w2);
    const unsigned long long w3p = pk2(w3, w3);
    const unsigned long long one2 = pk2(1.0f, 1.0f);
    const unsigned long long m12  = pk2(-1.0f, -1.0f);

    if (stride == 2) {
        int h = zb >> 1;
        float eA = (h >= 1) ? Ecol[(h - 1) * HW] : 0.f;
        float eB = (h < NS) ? Ecol[h * HW] : 0.f;
        float eC = (h + 1 < NS) ? Ecol[(h + 1) * HW] : 0.f;

        #pragma unroll 2
        for (int t = 0; t < UPD_CHUNK / 2; ++t, ++h) {
            const int z = zb + 2 * t;
            loadPair(t + 2, (t + 2) % 3);       // planes z+3, z+4
            const int b0i = t % 3, b1i = (t + 1) % 3;

            const float2 c0 = sp[b0i][ty + 1][tx + 1];   // (z-1, z)
            const float2 c1 = sp[b1i][ty + 1][tx + 1];   // (z+1, z+2)

            float ge = 0.f, go = 0.f;
            if (interior_xy) {
                const unsigned long long v0p = pk2(c0.y, c1.x);
                unsigned long long acc = pk2(0.0f, 0.0f);
                #pragma unroll
                for (int j = 0; j < 9; ++j) {
                    const int jy = j / 3, jx = j % 3;
                    const int dy = jy - 1, dx = jx - 1;
                    const int d2 = dy * dy + dx * dx;
                    const unsigned long long wa =
                        (d2 == 0) ? w1p : ((d2 == 1) ? w2p : w3p);
                    const float2 m  = sp[b0i][ty + jy][tx + jx];
                    const float2 pp = sp[b1i][ty + jy][tx + jx];
                    {   // dz = -1 : (A_even, A_odd) = (m.x, m.y)
                        const unsigned long long np = pk2(m.x, m.y);
                        const unsigned long long dv = fma2_(np, m12, v0p);
                        const unsigned long long tt = mul2_(dv, wa);
                        const unsigned long long ar = fma2_(dv, tt, one2);
                        float a0, a1; upk2(ar, a0, a1);
                        acc = fma2_(tt, pk2(rsqrtf(a0), rsqrtf(a1)), acc);
                    }
                    {   // dz = +1 : (C_even, C_odd) = (pp.x, pp.y)
                        const unsigned long long np = pk2(pp.x, pp.y);
                        const unsigned long long dv = fma2_(np, m12, v0p);
                        const unsigned long long tt = mul2_(dv, wa);
                        const unsigned long long ar = fma2_(dv, tt, one2);
                        float a0, a1; upk2(ar, a0, a1);
                        acc = fma2_(tt, pk2(rsqrtf(a0), rsqrtf(a1)), acc);
                    }
                    if (j != 4) {  // dz = 0 : (B_even, B_odd) = (m.y, pp.x)
                        const unsigned long long wb = (d2 == 1) ? w1p : w2p;
                        const unsigned long long np = pk2(m.y, pp.x);
                        const unsigned long long dv = fma2_(np, m12, v0p);
                        const unsigned long long tt = mul2_(dv, wb);
                        const unsigned long long ar = fma2_(dv, tt, one2);
                        float a0, a1; upk2(ar, a0, a1);
                        acc = fma2_(tt, pk2(rsqrtf(a0), rsqrtf(a1)), acc);
                    }
                }
                upk2(acc, ge, go);
                if (z == 0) ge = 0.f;
                if (z + 1 == D - 1) go = 0.f;
            }

            // ---- even z ----
            {
                float gd = fmaf(p0, eA, fmaf(p2, eB, p4 * eC));
                float xn = c0.y - ALPHA * (gd + BETA * ge);
                if (do_relu) xn = fmaxf(xn, 0.f);
                outcol[z * HW] = xn;
            }
            // ---- odd z+1 ----
            {
                float gd = fmaf(p1, eB, p3 * eC);
                float xn = c1.x - ALPHA * (gd + BETA * go);
                if (do_relu) xn = fmaxf(xn, 0.f);
                outcol[(z + 1) * HW] = xn;
            }

            eA = eB; eB = eC;
            eC = (h + 2 < NS) ? Ecol[(h + 2) * HW] : 0.f;
            __syncthreads();
        }
    } else {
        // generic-stride fallback (scalar), reading planes from pair buffers:
        // pair t: (.x = zb-1+2t, .y = zb+2t)
        for (int t = 0; t < UPD_CHUNK / 2; ++t) {
            const int z = zb + 2 * t;
            loadPair(t + 2, (t + 2) % 3);
            const int b0i = t % 3, b1i = (t + 1) % 3;

            #pragma unroll
            for (int s = 0; s < 2; ++s) {
                const int zz0 = z + s;
                // planes for voxel zz0: zm = zz0-1, zc = zz0, zp = zz0+1
                float ge = 0.f;
                const float2 cc0 = sp[b0i][ty + 1][tx + 1];
                const float2 cc1 = sp[b1i][ty + 1][tx + 1];
                const float v0 = s ? cc1.x : cc0.y;
                if (interior_xy && zz0 > 0 && zz0 < D - 1) {
                    #pragma unroll
                    for (int j = 0; j < 9; ++j) {
                        const int jy = j / 3, jx = j % 3;
                        const int dy = jy - 1, dx = jx - 1;
                        const int d2 = dy * dy + dx * dx;
                        const float wa = (d2 == 0) ? w1 : ((d2 == 1) ? w2 : w3);
                        const float2 m  = sp[b0i][ty + jy][tx + jx];
                        const float2 pp = sp[b1i][ty + jy][tx + jx];
                        const float Av = s ? m.y : m.x;
                        const float Bv = s ? pp.x : m.y;
                        const float Cv = s ? pp.y : pp.x;
                        { float dv = v0 - Av; float tt = dv * wa; ge += tt * rsqrtf(fmaf(dv, tt, 1.0f)); }
                        { float dv = v0 - Cv; float tt = dv * wa; ge += tt * rsqrtf(fmaf(dv, tt, 1.0f)); }
                        if (j != 4) {
                            const float wb = (d2 == 1) ? w1 : w2;
                            float dv = v0 - Bv; float tt = dv * wb;
                            ge += tt * rsqrtf(fmaf(dv, tt, 1.0f));
                        }
                    }
                }
                float gd = 0.f;
                #pragma unroll
                for (int dz = 0; dz < 5; ++dz) {
                    int zz = zz0 + dz - 2;
                    if ((unsigned)zz < (unsigned)D && (zz % stride) == 0) {
                        int pi = zz / stride;
                        if (pi < NS) gd = fmaf(d_p[dz], Ecol[pi * HW], gd);
                    }
                }
                float xn = v0 - ALPHA * (gd + BETA * ge);
                if (do_relu) xn = fmaxf(xn, 0.f);
                outcol[zz0 * HW] = xn;
            }
            __syncthreads();
        }
    }
}

// ===========================================================================
// Generic fallback kernels (runtime dims) — validated in R4/R5.
// ===========================================================================

__global__ __launch_bounds__(256) void fused_E_gen(
    const float* __restrict__ x, const float* __restrict__ slices,
    float* __restrict__ E, const int* __restrict__ stridep,
    int D, int H, int W, int n_slices) {
    __shared__ float sZ[40][44];
    __shared__ float sA[40][36];
    __shared__ float sF[36][36];
    __shared__ float sB[36][33];

    const int i = blockIdx.z;
    const int zi = i * (*stridep);
    const int x0 = blockIdx.x * 32, y0 = blockIdx.y * 32;
    const int tx = threadIdx.x, ty = threadIdx.y;
    const size_t HW = (size_t)H * W;

    const float p0 = d_p[0], p1 = d_p[1], p2 = d_p[2], p3 = d_p[3], p4 = d_p[4];

    {
        const int z0 = zi - 2;
        const bool zok0 = (z0 >= 0), zok1 = (z0 + 1 >= 0);
        const bool zok2 = (z0 + 2 >= 0) && (z0 + 2 < D);
        const bool zok3 = (z0 + 3 < D), zok4 = (z0 + 4 < D);
        #pragma unroll
        for (int k = 0; k < 5; ++k) {
            const int r = ty + 8 * k;
            const int gy = y0 - 4 + r;
            const bool okY = (unsigned)gy < (unsigned)H;
            #pragma unroll
            for (int b = 0; b < 2; ++b) {
                const int c = b * 32 + tx;
                if (b == 1 && tx >= 8) break;
                const int gx = x0 - 4 + c;
                float acc = 0.f;
                if (okY && (unsigned)gx < (unsigned)W) {
                    const float* col = x + (size_t)gy * W + gx + (size_t)z0 * HW;
                    if (zok0) acc = fmaf(p0, col[0], acc);
                    if (zok1) acc = fmaf(p1, col[HW], acc);
                    if (zok2) acc = fmaf(p2, col[2 * HW], acc);
                    if (zok3) acc = fmaf(p3, col[3 * HW], acc);
                    if (zok4) acc = fmaf(p4, col[4 * HW], acc);
                }
                sZ[r][c] = acc;
            }
        }
    }
    __syncthreads();

    #pragma unroll
    for (int k = 0; k < 5; ++k) {
        const int r = ty + 8 * k;
        sA[r][tx] = p0 * sZ[r][tx]     + p1 * sZ[r][tx + 1] + p2 * sZ[r][tx + 2]
                  + p3 * sZ[r][tx + 3] + p4 * sZ[r][tx + 4];
        if (tx < 4) {
            const int c = 32 + tx;
            sA[r][c] = p0 * sZ[r][c]     + p1 * sZ[r][c + 1] + p2 * sZ[r][c + 2]
                     + p3 * sZ[r][c + 3] + p4 * sZ[r][c + 4];
        }
    }
    __syncthreads();

    {
        const float* sl = slices + (size_t)i * HW;
        #pragma unroll
        for (int k = 0; k < 5; ++k) {
            const int r = (k < 4) ? (ty + 8 * k) : (32 + ty);
            if (k == 4 && ty >= 4) break;
            const int gy = y0 - 2 + r;
            const bool okY = (unsigned)gy < (unsigned)H;
            #pragma unroll
            for (int b = 0; b < 2; ++b) {
                const int c = b * 32 + tx;
                if (b == 1 && tx >= 4) break;
                const int gx = x0 - 2 + c;
                float v = 0.f;
                if (okY && (unsigned)gx < (unsigned)W) {
                    v = p0 * sA[r][c]     + p1 * sA[r + 1][c] + p2 * sA[r + 2][c]
                      + p3 * sA[r + 3][c] + p4 * sA[r + 4][c]
                      - sl[(size_t)gy * W + gx];
                }
                sF[r][c] = v;
            }
        }
    }
    __syncthreads();

    #pragma unroll
    for (int k = 0; k < 5; ++k) {
        const int r = (k < 4) ? (ty + 8 * k) : (32 + ty);
        if (k == 4 && ty >= 4) break;
        sB[r][tx] = p0 * sF[r][tx]     + p1 * sF[r][tx + 1] + p2 * sF[r][tx + 2]
                  + p3 * sF[r][tx + 3] + p4 * sF[r][tx + 4];
    }
    __syncthreads();

    {
        float* Ei = E + (size_t)i * HW;
        #pragma unroll
        for (int k = 0; k < 4; ++k) {
            const int r = ty + 8 * k;
            const int gy = y0 + r, gx = x0 + tx;
            if (gy < H && gx < W) {
                Ei[(size_t)gy * W + gx] =
                      p0 * sB[r][tx]     + p1 * sB[r + 1][tx] + p2 * sB[r + 2][tx]
                    + p3 * sB[r + 3][tx] + p4 * sB[r + 4][tx];
            }
        }
    }
}

__global__ __launch_bounds__(256, 4) void update_gen(
    const float* __restrict__ xin, const float* __restrict__ E,
    float* __restrict__ xout, const int* __restrict__ stridep,
    int n_slices, int D, int H, int W, int do_relu) {
    __shared__ float s[3][10][36];

    const int x0 = blockIdx.x * 32, y0 = blockIdx.y * 8;
    const int zb = blockIdx.z * UPD_CHUNK;
    const int tx = threadIdx.x, ty = threadIdx.y;
    const int tid = ty * 32 + tx;
    const size_t HW = (size_t)H * W;
    const int y = y0 + ty, x = x0 + tx;
    const int stride = *stridep;

    const float p0 = d_p[0], p1 = d_p[1], p2 = d_p[2], p3 = d_p[3], p4 = d_p[4];
    const float pz[5] = {p0, p1, p2, p3, p4};
    const float w1 = (float)(1.0 / (1.0 * 0.1 * 0.1));
    const float w2 = (float)(1.0 / (2.0 * 0.1 * 0.1));
    const float w3 = (float)(1.0 / (3.0 * 0.1 * 0.1));

    const int ly0 = tid / 34, lx0 = tid % 34;
    const int gy0 = y0 - 1 + ly0, gx0 = x0 - 1 + lx0;
    const bool ok0 = (unsigned)gy0 < (unsigned)H && (unsigned)gx0 < (unsigned)W;
    const size_t off0 = ok0 ? ((size_t)gy0 * W + gx0) : 0;
    const int i1 = tid + 256;
    const bool has1 = (i1 < 340);
    const int ly1 = has1 ? i1 / 34 : 0, lx1 = has1 ? i1 % 34 : 0;
    const int gy1 = y0 - 1 + ly1, gx1 = x0 - 1 + lx1;
    const bool ok1 = has1 && (unsigned)gy1 < (unsigned)H && (unsigned)gx1 < (unsigned)W;
    const size_t off1 = ok1 ? ((size_t)gy1 * W + gx1) : 0;

    auto loadPlane = [&](int z, int sl) {
        const bool zok = (unsigned)z < (unsigned)D;
        const size_t zo = (size_t)(zok ? z : 0) * HW;
        s[sl][ly0][lx0] = (zok && ok0) ? xin[zo + off0] : 0.f;
        if (has1) s[sl][ly1][lx1] = (zok && ok1) ? xin[zo + off1] : 0.f;
    };

    const int sl_m1 = ((zb - 1) % 3 + 3) % 3;
    const int sl_0  = zb % 3;
    loadPlane(zb - 1, sl_m1);
    loadPlane(zb, sl_0);
    __syncthreads();

    float A[9], B[9];
    #pragma unroll
    for (int dy = 0; dy < 3; ++dy)
        #pragma unroll
        for (int dx = 0; dx < 3; ++dx) {
            A[dy * 3 + dx] = s[sl_m1][ty + dy][tx + dx];
            B[dy * 3 + dx] = s[sl_0][ty + dy][tx + dx];
        }

    const bool interior_xy = (y > 0 && y < H - 1 && x > 0 && x < W - 1);
    const size_t eo = (size_t)y * W + x;
    const float* Ecol = E + eo;
    float* outcol = xout + eo;
    const float ALPHA = 0.5f;
    const float BETA = (float)(0.02 * 0.1 * 0.1);

    int zend = zb + UPD_CHUNK;
    if (zend > D) zend = D;

    for (int z = zb; z < zend; ++z) {
        const int sl = (z + 1) % 3;
        loadPlane(z + 1, sl);
        __syncthreads();

        float C[9];
        #pragma unroll
        for (int dy = 0; dy < 3; ++dy)
            #pragma unroll
            for (int dx = 0; dx < 3; ++dx)
                C[dy * 3 + dx] = s[sl][ty + dy][tx + dx];

        const float v0 = B[4];
        float gd = 0.f;
        #pragma unroll
        for (int dz = 0; dz < 5; ++dz) {
            int zz = z + dz - 2;
            if ((unsigned)zz < (unsigned)D && (zz % stride) == 0) {
                int pi = zz / stride;
                if (pi < n_slices) gd = fmaf(pz[dz], Ecol[(size_t)pi * HW], gd);
            }
        }

        float greg = 0.f;
        if (interior_xy && z > 0 && z < D - 1) {
            #pragma unroll
            for (int j = 0; j < 9; ++j) {
                const int dy = j / 3 - 1, dx = j % 3 - 1;
                const int d2a = dy * dy + dx * dx + 1;
                const float wa = (d2a == 1) ? w1 : ((d2a == 2) ? w2 : w3);
                { float dv = v0 - A[j]; float t = dv * wa; greg += t * rsqrtf(fmaf(dv, t, 1.0f)); }
                { float dv = v0 - C[j]; float t = dv * wa; greg += t * rsqrtf(fmaf(dv, t, 1.0f)); }
                if (j != 4) {
                    const int d2b = dy * dy + dx * dx;
                    const float wb = (d2b == 1) ? w1 : ((d2b == 2) ? w2 : w3);
                    float dv = v0 - B[j]; float t = dv * wb;
                    greg += t * rsqrtf(fmaf(dv, t, 1.0f));
                }
            }
        }

        float xn = v0 - ALPHA * (gd + BETA * greg);
        if (do_relu) xn = fmaxf(xn, 0.f);
        outcol[(size_t)z * HW] = xn;

        #pragma unroll
        for (int j = 0; j < 9; ++j) { A[j] = B[j]; B[j] = C[j]; }
    }
}

// ---------------------------------------------------------------------------
extern "C" void kernel_launch(void* const* d_in, const int* in_sizes, int n_in,
                              void* d_out, int out_size) {
    const float* slices = (const float*)d_in[1];
    const float* volume = (const float*)d_in[2];
    const float* psf    = (const float*)d_in[3];
    const int* stridep  = (const int*)d_in[4];

    int D = (int)lround(cbrt((double)out_size));   // 192
    int H = D, W = D;
    int n_slices = in_sizes[1] / (H * W);

    float *pE, *pA, *pB;
    cudaGetSymbolAddress((void**)&pE, d_E);
    cudaGetSymbolAddress((void**)&pA, d_A);
    cudaGetSymbolAddress((void**)&pB, d_B);

    init_p_kernel<<<1, 32>>>(psf);

    const bool spec = (D == 192 && H == 192 && W == 192 && n_slices == 96);

    dim3 blkE(32, 8, 1);
    dim3 grid_E2((W + 31) / 32, (H + 31) / 32, n_slices / 2);
    dim3 grid_E((W + 31) / 32, (H + 31) / 32, n_slices);
    dim3 blkU(32, 8, 1);
    dim3 grid_up((W + 31) / 32, (H + 7) / 8, (D + UPD_CHUNK - 1) / UPD_CHUNK);

    if (spec) {
        stilde_t<192, 192><<<dim3(6, 6, 96), blkE>>>(slices, pB);
        for (int it = 0; it < N_ITER; ++it) {
            const float* xin = (it == 0) ? volume
                                         : ((it & 1) ? pA : (const float*)d_out);
            float* xout = (it & 1) ? (float*)d_out : pA;
            int do_relu = (it == N_ITER - 1) ? 1 : 0;
            fused_E3_t<192, 192, 192, 96><<<grid_E2, blkE>>>(xin, pB, pE, stridep);
            update3_t<192, 192, 192, 96><<<grid_up, blkU>>>(xin, pE, xout, stridep, do_relu);
        }
    } else {
        for (int it = 0; it < N_ITER; ++it) {
            const float* xin = (it == 0) ? volume : ((it & 1) ? pA : pB);
            float* xout = (it == N_ITER - 1) ? (float*)d_out
                                             : ((it & 1) ? pB : pA);
            int do_relu = (it == N_ITER - 1) ? 1 : 0;
            fused_E_gen<<<grid_E, blkE>>>(xin, slices, pE, stridep, D, H, W, n_slices);
            update_gen<<<grid_up, blkU>>>(xin, pE, xout, stridep, n_slices, D, H, W, do_relu);
        }
    }
}